// round 9
// baseline (speedup 1.0000x reference)
#include <cuda_runtime.h>
#include <cuda_fp16.h>
#include <stdint.h>

#define BATCH 4
#define SEQ   2048
#define DIM   1024
#define NH    16
#define HD    64
#define SCALE 0.125f
#define MTOT  (BATCH*SEQ)

// ---- scratch ----
__device__ __half g_q[MTOT * DIM];
__device__ __half g_k[MTOT * DIM];
__device__ __half g_v[MTOT * DIM];    // [b*S+s][n]  (temp)
__device__ __half g_vT[MTOT * DIM];   // [(b*NH+h)*HD+d][s]
__device__ __half g_ctx[MTOT * DIM];
__device__ __half g_x[MTOT * DIM];
__device__ __half g_w[4 * DIM * DIM]; // W^T, [n][k]
__device__ __half g_r[(size_t)BATCH * SEQ * SEQ];  // 1/Z, fp16

// ---- helpers ----
__device__ __forceinline__ uint32_t h2u(float a, float b) {
    __half2 h = __floats2half2_rn(a, b);
    return *(uint32_t*)&h;
}
__device__ __forceinline__ void mma16(float c[4], const uint32_t a[4], const uint32_t b[2]) {
    asm volatile(
        "mma.sync.aligned.m16n8k16.row.col.f32.f16.f16.f32 "
        "{%0,%1,%2,%3}, {%4,%5,%6,%7}, {%8,%9}, {%0,%1,%2,%3};\n"
        : "+f"(c[0]), "+f"(c[1]), "+f"(c[2]), "+f"(c[3])
        : "r"(a[0]), "r"(a[1]), "r"(a[2]), "r"(a[3]), "r"(b[0]), "r"(b[1]));
}
__device__ __forceinline__ void ldsm4(uint32_t r[4], const uint32_t* p) {
    uint32_t a = (uint32_t)__cvta_generic_to_shared(p);
    asm volatile("ldmatrix.sync.aligned.m8n8.x4.shared.b16 {%0,%1,%2,%3}, [%4];\n"
                 : "=r"(r[0]), "=r"(r[1]), "=r"(r[2]), "=r"(r[3]) : "r"(a));
}
__device__ __forceinline__ void cpa16(void* s, const void* g) {
    uint32_t sa = (uint32_t)__cvta_generic_to_shared(s);
    asm volatile("cp.async.ca.shared.global [%0], [%1], 16;\n" ::"r"(sa), "l"(g));
}
__device__ __forceinline__ void cp_commit() { asm volatile("cp.async.commit_group;\n"); }
template <int N>
__device__ __forceinline__ void cp_wait() { asm volatile("cp.async.wait_group %0;\n" ::"n"(N)); }

// =====================================================================
// x -> fp16
// =====================================================================
__global__ void round_x_h(const float* __restrict__ x) {
    const int n4 = MTOT * DIM / 4;
    uint2* out = (uint2*)g_x;
    int i = blockIdx.x * blockDim.x + threadIdx.x;
    int stride = gridDim.x * blockDim.x;
    for (; i < n4; i += stride) {
        float4 v = ((const float4*)x)[i];
        uint2 o;
        o.x = h2u(v.x, v.y);
        o.y = h2u(v.z, v.w);
        out[i] = o;
    }
}

// =====================================================================
// weights -> fp16, transposed to [n][k]
// =====================================================================
__global__ void round_w_t(const float* __restrict__ w0, const float* __restrict__ w1,
                          const float* __restrict__ w2, const float* __restrict__ w3) {
    __shared__ float t[32][33];
    const float* src = (blockIdx.z == 0) ? w0 : (blockIdx.z == 1) ? w1 : (blockIdx.z == 2) ? w2 : w3;
    __half* dst = g_w + (size_t)blockIdx.z * DIM * DIM;
    const int k0 = blockIdx.y * 32, n0 = blockIdx.x * 32;
    const int r = threadIdx.x >> 5, cc = threadIdx.x & 31;
#pragma unroll
    for (int i = 0; i < 4; i++) t[r + i * 8][cc] = src[(size_t)(k0 + r + i * 8) * DIM + n0 + cc];
    __syncthreads();
#pragma unroll
    for (int i = 0; i < 4; i++)
        dst[(size_t)(n0 + r + i * 8) * DIM + k0 + cc] = __float2half_rn(t[cc][r + i * 8]);
}

// =====================================================================
// v [s][n] -> vT [n][s], per batch
// =====================================================================
__global__ void transpose_v() {
    __shared__ __half t[32][33];
    const int b = blockIdx.z, s0 = blockIdx.x * 32, n0 = blockIdx.y * 32;
    const int r = threadIdx.x >> 5, cc = threadIdx.x & 31;
#pragma unroll
    for (int i = 0; i < 4; i++)
        t[r + i * 8][cc] = g_v[(size_t)(b * SEQ + s0 + r + i * 8) * DIM + n0 + cc];
    __syncthreads();
#pragma unroll
    for (int i = 0; i < 4; i++)
        g_vT[((size_t)b * DIM + n0 + r + i * 8) * SEQ + s0 + cc] = t[cc][r + i * 8];
}

// =====================================================================
// GEMM: C[M,1024] = A @ W  (A fp16 [m][k], W as W^T fp16 [n][k]).
// Block 128x256, k-stage 64, 8 warps (2m x 4n), warp 64x64, GS=3.
// LDSM + register double-buffered fragments.
// =====================================================================
#define GS 3
#define GA_W (128 * 36)
#define GB_W (256 * 36)
#define G_SMEM (GS * (GA_W + GB_W) * 4)

__global__ __launch_bounds__(256) void gemm_fp16(const __half* __restrict__ A,
                                                 const __half* __restrict__ WT,
                                                 void* __restrict__ Cout, int half_out) {
    extern __shared__ uint32_t smu[];
    uint32_t* sA = smu;
    uint32_t* sB = smu + GS * GA_W;
    const int tid = threadIdx.x;
    const int m0 = blockIdx.y * 128, n0 = blockIdx.x * 256;
    const int w = tid >> 5, lane = tid & 31, g = lane >> 2, tg = lane & 3;
    const int wm = (w >> 2) * 64, wn = (w & 3) * 64;
    const int lrA = (lane & 7) + ((lane >> 3) & 1) * 8, lcA = (lane >> 4) * 4;
    const int lrB = (lane & 7) + (lane >> 4) * 8, lcB = ((lane >> 3) & 1) * 4;

    float acc[4][8][4]{};

    auto load_tile = [&](int st, int kt) {
        uint32_t* a = sA + st * GA_W;
        uint32_t* bb = sB + st * GB_W;
#pragma unroll
        for (int i = 0; i < 4; i++) {
            int c = tid + 256 * i;
            int r = c >> 3, cw = (c & 7) * 4;
            cpa16(a + r * 36 + cw, A + (size_t)(m0 + r) * DIM + kt + cw * 2);
        }
#pragma unroll
        for (int i = 0; i < 8; i++) {
            int c = tid + 256 * i;
            int r = c >> 3, cw = (c & 7) * 4;
            cpa16(bb + r * 36 + cw, WT + (size_t)(n0 + r) * DIM + kt + cw * 2);
        }
    };

    const int NK = DIM / 64;  // 16
#pragma unroll
    for (int s = 0; s < GS - 1; s++) {
        load_tile(s, s * 64);
        cp_commit();
    }
    uint32_t af[2][4][4], bf[2][8][2];

    auto load_frag = [&](const uint32_t* a, const uint32_t* b, int kw, int buf) {
#pragma unroll
        for (int mt = 0; mt < 4; mt++)
            ldsm4(af[buf][mt], a + (wm + mt * 16 + lrA) * 36 + kw + lcA);
#pragma unroll
        for (int np = 0; np < 4; np++) {
            uint32_t tmp[4];
            ldsm4(tmp, b + (wn + np * 16 + lrB) * 36 + kw + lcB);
            bf[buf][2 * np][0] = tmp[0];
            bf[buf][2 * np][1] = tmp[1];
            bf[buf][2 * np + 1][0] = tmp[2];
            bf[buf][2 * np + 1][1] = tmp[3];
        }
    };

    for (int t = 0; t < NK; t++) {
        cp_wait<GS - 2>();
        __syncthreads();
        int ld = t + GS - 1;
        if (ld < NK) load_tile(ld % GS, ld * 64);
        cp_commit();
        const uint32_t* a = sA + (t % GS) * GA_W;
        const uint32_t* b = sB + (t % GS) * GB_W;
        load_frag(a, b, 0, 0);
#pragma unroll
        for (int k8 = 0; k8 < 4; k8++) {
            int cur = k8 & 1;
            if (k8 < 3) load_frag(a, b, (k8 + 1) * 8, cur ^ 1);
#pragma unroll
            for (int mt = 0; mt < 4; mt++)
#pragma unroll
                for (int nt = 0; nt < 8; nt++) mma16(acc[mt][nt], af[cur][mt], bf[cur][nt]);
        }
    }
#pragma unroll
    for (int mt = 0; mt < 4; mt++)
#pragma unroll
        for (int nt = 0; nt < 8; nt++) {
            int row = m0 + wm + mt * 16 + g;
            int col = n0 + wn + nt * 8 + 2 * tg;
            if (half_out) {
                __half* C = (__half*)Cout;
                *(uint32_t*)(C + (size_t)row * DIM + col) = h2u(acc[mt][nt][0], acc[mt][nt][1]);
                *(uint32_t*)(C + (size_t)(row + 8) * DIM + col) = h2u(acc[mt][nt][2], acc[mt][nt][3]);
            } else {
                float* C = (float*)Cout;
                *(float2*)(C + (size_t)row * DIM + col) = make_float2(acc[mt][nt][0], acc[mt][nt][1]);
                *(float2*)(C + (size_t)(row + 8) * DIM + col) = make_float2(acc[mt][nt][2], acc[mt][nt][3]);
            }
        }
}

// =====================================================================
// Pass A: R = 1 / sum_h exp(scale q.k)   (fp16 MMA, LDSM, frag dbuf)
// =====================================================================
#define ZT_W (128 * 36)
#define Z_SMEM (4 * ZT_W * 4)

__global__ __launch_bounds__(256) void attn_z() {
    extern __shared__ uint32_t smu[];
    uint32_t* sQ = smu;
    uint32_t* sK = smu + 2 * ZT_W;
    const int tid = threadIdx.x;
    const int b = blockIdx.z, qt = blockIdx.y * 128, kt = blockIdx.x * 128;
    const int w = tid >> 5, lane = tid & 31, g = lane >> 2, tg = lane & 3;
    const int wm = (w >> 2) * 64, wn = (w & 3) * 32;
    const int lrA = (lane & 7) + ((lane >> 3) & 1) * 8, lcA = (lane >> 4) * 4;
    const int lrB = (lane & 7) + (lane >> 4) * 8, lcB = ((lane >> 3) & 1) * 4;

    const __half* qb = g_q + (size_t)(b * SEQ + qt) * DIM;
    const __half* kb = g_k + (size_t)(b * SEQ + kt) * DIM;

    auto load_head = [&](int st, int h) {
        uint32_t* q = sQ + st * ZT_W;
        uint32_t* k = sK + st * ZT_W;
#pragma unroll
        for (int i = 0; i < 4; i++) {
            int c = tid + 256 * i;
            int r = c >> 3, cw = (c & 7) * 4;
            cpa16(q + r * 36 + cw, qb + (size_t)r * DIM + h * HD + cw * 2);
            cpa16(k + r * 36 + cw, kb + (size_t)r * DIM + h * HD + cw * 2);
        }
    };

    float zacc[4][4][4]{};
    load_head(0, 0);
    cp_commit();

    uint32_t af[2][4][4], bf[2][4][2];
    auto load_frag = [&](const uint32_t* q, const uint32_t* k, int kw, int buf) {
#pragma unroll
        for (int mt = 0; mt < 4; mt++)
            ldsm4(af[buf][mt], q + (wm + mt * 16 + lrA) * 36 + kw + lcA);
#pragma unroll
        for (int np = 0; np < 2; np++) {
            uint32_t tmp[4];
            ldsm4(tmp, k + (wn + np * 16 + lrB) * 36 + kw + lcB);
            bf[buf][2 * np][0] = tmp[0];
            bf[buf][2 * np][1] = tmp[1];
            bf[buf][2 * np + 1][0] = tmp[2];
            bf[buf][2 * np + 1][1] = tmp[3];
        }
    };

    for (int h = 0; h < NH; h++) {
        cp_wait<0>();
        __syncthreads();
        if (h + 1 < NH) load_head((h + 1) & 1, h + 1);
        cp_commit();
        const uint32_t* q = sQ + (h & 1) * ZT_W;
        const uint32_t* k = sK + (h & 1) * ZT_W;

        float sacc[4][4][4]{};
        load_frag(q, k, 0, 0);
#pragma unroll
        for (int k8 = 0; k8 < 4; k8++) {
            int cur = k8 & 1;
            if (k8 < 3) load_frag(q, k, (k8 + 1) * 8, cur ^ 1);
#pragma unroll
            for (int mt = 0; mt < 4; mt++)
#pragma unroll
                for (int nt = 0; nt < 4; nt++) mma16(sacc[mt][nt], af[cur][mt], bf[cur][nt]);
        }
#pragma unroll
        for (int i = 0; i < 4; i++)
#pragma unroll
            for (int j = 0; j < 4; j++)
#pragma unroll
                for (int e = 0; e < 4; e++) zacc[i][j][e] += __expf(sacc[i][j][e] * SCALE);
    }
#pragma unroll
    for (int mt = 0; mt < 4; mt++)
#pragma unroll
        for (int nt = 0; nt < 4; nt++) {
            int row = qt + wm + mt * 16 + g;
            int col = kt + wn + nt * 8 + 2 * tg;
            __half* rp = g_r + ((size_t)b * SEQ + row) * SEQ + col;
            *(uint32_t*)rp = h2u(1.f / zacc[mt][nt][0], 1.f / zacc[mt][nt][1]);
            *(uint32_t*)(rp + (size_t)8 * SEQ) = h2u(1.f / zacc[mt][nt][2], 1.f / zacc[mt][nt][3]);
        }
}

// =====================================================================
// Pass B: ctx = sum_k exp(scale*S)*R * V  per (b,h,qtile)  (fp16, LDSM)
// h = blockIdx.x: adjacent CTAs share the same R slab (L2 reuse).
// =====================================================================
#define CQ_W (128 * 36)
#define CVT_W (64 * 68)
#define CP_W (128 * 68)
#define CR_W (128 * 68)   // fp16 R tile: 128 x 136 halves
#define C_SMEM ((3 * CQ_W + CVT_W + CP_W + CR_W) * 4)

__global__ __launch_bounds__(256) void attn_ctx() {
    extern __shared__ uint32_t smu[];
    uint32_t* sQ = smu;
    uint32_t* sK = smu + CQ_W;  // [2]
    uint32_t* sVT = smu + 3 * CQ_W;
    uint32_t* sP = sVT + CVT_W;
    __half* sRh = (__half*)(sP + CP_W);  // [128][136] halves
    float* sRf = (float*)sRh;

    const int tid = threadIdx.x;
    const int b = blockIdx.z, h = blockIdx.x, qt = blockIdx.y * 128;
    const int w = tid >> 5, lane = tid & 31, g = lane >> 2, tg = lane & 3;
    const int wm = (w >> 2) * 64, wn = (w & 3) * 32;
    const int wk2 = (w >> 1) & 1, wn2 = (w & 1) * 32;
    const int lrA = (lane & 7) + ((lane >> 3) & 1) * 8, lcA = (lane >> 4) * 4;
    const int lrB = (lane & 7) + (lane >> 4) * 8, lcB = ((lane >> 3) & 1) * 4;

    const __half* qb = g_q + (size_t)(b * SEQ + qt) * DIM + h * HD;
#pragma unroll
    for (int i = 0; i < 4; i++) {
        int c = tid + 256 * i;
        int r = c >> 3, cw = (c & 7) * 4;
        cpa16(sQ + r * 36 + cw, qb + (size_t)r * DIM + cw * 2);
    }
    {
        const __half* kb = g_k + (size_t)(b * SEQ) * DIM + h * HD;
#pragma unroll
        for (int i = 0; i < 4; i++) {
            int c = tid + 256 * i;
            int r = c >> 3, cw = (c & 7) * 4;
            cpa16(sK + r * 36 + cw, kb + (size_t)r * DIM + cw * 2);
        }
    }
    cp_commit();

    float cacc[4][4][4]{};

    for (int t = 0; t < SEQ / 128; t++) {
        const int kt = t * 128;
        {
            const __half* vtb = g_vT + ((size_t)(b * NH + h) * HD) * SEQ + kt;
#pragma unroll
            for (int i = 0; i < 4; i++) {
                int c = tid + 256 * i;
                int r = c >> 4, cw = (c & 15) * 4;
                cpa16(sVT + r * 68 + cw, vtb + (size_t)r * SEQ + cw * 2);
            }
            const __half* rb = g_r + ((size_t)b * SEQ + qt) * SEQ + kt;
#pragma unroll
            for (int i = 0; i < 8; i++) {
                int c = tid + 256 * i;
                int r = c >> 4, ch = (c & 15) * 8;
                cpa16(sRh + r * 136 + ch, rb + (size_t)r * SEQ + ch);
            }
        }
        cp_commit();
        cp_wait<1>();  // K(t) (and Q) ready
        __syncthreads();

        {
            int ktn = (t + 1 < SEQ / 128) ? kt + 128 : 0;
            const __half* kb = g_k + (size_t)(b * SEQ + ktn) * DIM + h * HD;
            uint32_t* kd = sK + ((t + 1) & 1) * CQ_W;
#pragma unroll
            for (int i = 0; i < 4; i++) {
                int c = tid + 256 * i;
                int r = c >> 3, cw = (c & 7) * 4;
                cpa16(kd + r * 36 + cw, kb + (size_t)r * DIM + cw * 2);
            }
        }
        cp_commit();

        // GEMM1: S = Q @ K^T (128x128x64)
        const uint32_t* kc = sK + (t & 1) * CQ_W;
        float sacc[4][4][4]{};
#pragma unroll
        for (int kw = 0; kw < 32; kw += 8) {
            uint32_t af[4][4], bf[4][2];
#pragma unroll
            for (int mt = 0; mt < 4; mt++)
                ldsm4(af[mt], sQ + (wm + mt * 16 + lrA) * 36 + kw + lcA);
#pragma unroll
            for (int np = 0; np < 2; np++) {
                uint32_t tmp[4];
                ldsm4(tmp, kc + (wn + np * 16 + lrB) * 36 + kw + lcB);
                bf[2 * np][0] = tmp[0];
                bf[2 * np][1] = tmp[1];
                bf[2 * np + 1][0] = tmp[2];
                bf[2 * np + 1][1] = tmp[3];
            }
#pragma unroll
            for (int mt = 0; mt < 4; mt++)
#pragma unroll
                for (int nt = 0; nt < 4; nt++) mma16(sacc[mt][nt], af[mt], bf[nt]);
        }

        cp_wait<1>();  // V(t), R(t) ready
        __syncthreads();

        // P = fp16(exp(scale*S) * R) into sP
#pragma unroll
        for (int mt = 0; mt < 4; mt++)
#pragma unroll
            for (int nt = 0; nt < 4; nt++) {
                int row = wm + mt * 16 + g;
                int colh = wn + nt * 8 + 2 * tg;
                __half2 r0 = *(__half2*)(sRh + row * 136 + colh);
                __half2 r1 = *(__half2*)(sRh + (row + 8) * 136 + colh);
                float2 rf0 = __half22float2(r0), rf1 = __half22float2(r1);
                sP[row * 68 + (colh >> 1)] =
                    h2u(__expf(sacc[mt][nt][0] * SCALE) * rf0.x, __expf(sacc[mt][nt][1] * SCALE) * rf0.y);
                sP[(row + 8) * 68 + (colh >> 1)] =
                    h2u(__expf(sacc[mt][nt][2] * SCALE) * rf1.x, __expf(sacc[mt][nt][3] * SCALE) * rf1.y);
            }
        __syncthreads();

        // GEMM2: ctx += P @ V (128x64x128, k-split over warps)
#pragma unroll
        for (int kw = 0; kw < 32; kw += 8) {
            const int kx = wk2 * 32 + kw;
            uint32_t af[4][4], bf[4][2];
#pragma unroll
            for (int mt = 0; mt < 4; mt++)
                ldsm4(af[mt], sP + (wm + mt * 16 + lrA) * 68 + kx + lcA);
#pragma unroll
            for (int np = 0; np < 2; np++) {
                uint32_t tmp[4];
                ldsm4(tmp, sVT + (wn2 + np * 16 + lrB) * 68 + kx + lcB);
                bf[2 * np][0] = tmp[0];
                bf[2 * np][1] = tmp[1];
                bf[2 * np + 1][0] = tmp[2];
                bf[2 * np + 1][1] = tmp[3];
            }
#pragma unroll
            for (int mt = 0; mt < 4; mt++)
#pragma unroll
                for (int nt = 0; nt < 4; nt++) mma16(cacc[mt][nt], af[mt], bf[nt]);
        }
        __syncthreads();
    }

    // reduce k-split partials via sRf (R tile buffer, free now)
    if (wk2 == 1) {
#pragma unroll
        for (int mt = 0; mt < 4; mt++)
#pragma unroll
            for (int nt = 0; nt < 4; nt++) {
                int row = wm + mt * 16 + g;
                int col = wn2 + nt * 8 + 2 * tg;
                *(float2*)&sRf[row * 68 + col] = make_float2(cacc[mt][nt][0], cacc[mt][nt][1]);
                *(float2*)&sRf[(row + 8) * 68 + col] = make_float2(cacc[mt][nt][2], cacc[mt][nt][3]);
            }
    }
    __syncthreads();
    if (wk2 == 0) {
        __half* cb = g_ctx + (size_t)(b * SEQ + qt) * DIM + h * HD;
#pragma unroll
        for (int mt = 0; mt < 4; mt++)
#pragma unroll
            for (int nt = 0; nt < 4; nt++) {
                int row = wm + mt * 16 + g;
                int col = wn2 + nt * 8 + 2 * tg;
                float2 o0 = *(float2*)&sRf[row * 68 + col];
                float2 o1 = *(float2*)&sRf[(row + 8) * 68 + col];
                *(uint32_t*)(cb + (size_t)row * DIM + col) =
                    h2u(o0.x + cacc[mt][nt][0], o0.y + cacc[mt][nt][1]);
                *(uint32_t*)(cb + (size_t)(row + 8) * DIM + col) =
                    h2u(o1.x + cacc[mt][nt][2], o1.y + cacc[mt][nt][3]);
            }
    }
}

// =====================================================================
extern "C" void kernel_launch(void* const* d_in, const int* in_sizes, int n_in,
                              void* d_out, int out_size) {
    const float* x = (const float*)d_in[0];
    const float* wq = (const float*)d_in[1];
    const float* wk = (const float*)d_in[2];
    const float* wv = (const float*)d_in[3];
    const float* wo = (const float*)d_in[4];
    float* out = (float*)d_out;

    __half *q, *k, *v, *ctx, *xr, *wr;
    cudaGetSymbolAddress((void**)&q, g_q);
    cudaGetSymbolAddress((void**)&k, g_k);
    cudaGetSymbolAddress((void**)&v, g_v);
    cudaGetSymbolAddress((void**)&ctx, g_ctx);
    cudaGetSymbolAddress((void**)&xr, g_x);
    cudaGetSymbolAddress((void**)&wr, g_w);

    static int attr_done = 0;
    if (!attr_done) {
        cudaFuncSetAttribute(gemm_fp16, cudaFuncAttributeMaxDynamicSharedMemorySize, G_SMEM);
        cudaFuncSetAttribute(attn_z, cudaFuncAttributeMaxDynamicSharedMemorySize, Z_SMEM);
        cudaFuncSetAttribute(attn_ctx, cudaFuncAttributeMaxDynamicSharedMemorySize, C_SMEM);
        attr_done = 1;
    }

    round_x_h<<<2048, 256>>>(x);
    round_w_t<<<dim3(32, 32, 4), 256>>>(wq, wk, wv, wo);

    dim3 gg(DIM / 256, MTOT / 128);  // (4, 64)
    gemm_fp16<<<gg, 256, G_SMEM>>>(xr, wr + 0 * DIM * DIM, q, 1);
    gemm_fp16<<<gg, 256, G_SMEM>>>(xr, wr + 1 * DIM * DIM, k, 1);
    gemm_fp16<<<gg, 256, G_SMEM>>>(xr, wr + 2 * DIM * DIM, v, 1);

    transpose_v<<<dim3(SEQ / 32, DIM / 32, BATCH), 256>>>();

    attn_z<<<dim3(SEQ / 128, SEQ / 128, BATCH), 256, Z_SMEM>>>();

    attn_ctx<<<dim3(NH, SEQ / 128, BATCH), 256, C_SMEM>>>();

    gemm_fp16<<<gg, 256, G_SMEM>>>(ctx, wr + 3 * DIM * DIM, out, 0);
}

// round 10
// speedup vs baseline: 1.0302x; 1.0302x over previous
#include <cuda_runtime.h>
#include <cuda_fp16.h>
#include <stdint.h>

#define BATCH 4
#define SEQ   2048
#define DIM   1024
#define NH    16
#define HD    64
#define MTOT  (BATCH*SEQ)
// scale*log2(e): folded into q so 2^score = exp(0.125*qk)
#define QSCALE 0.1803368801111204f

// ---- scratch ----
__device__ __half g_q[MTOT * DIM];
__device__ __half g_k[MTOT * DIM];
__device__ __half g_v[MTOT * DIM];    // [b*S+s][n]  (temp)
__device__ __half g_vT[MTOT * DIM];   // [(b*NH+h)*HD+d][s]
__device__ __half g_ctx[MTOT * DIM];
__device__ __half g_x[MTOT * DIM];
__device__ __half g_w[4 * DIM * DIM]; // W^T, [n][k]
__device__ __half g_r[(size_t)BATCH * SEQ * SEQ];  // 1/Z, fp16

// ---- helpers ----
__device__ __forceinline__ uint32_t h2u(float a, float b) {
    __half2 h = __floats2half2_rn(a, b);
    return *(uint32_t*)&h;
}
__device__ __forceinline__ void mma16(float c[4], const uint32_t a[4], const uint32_t b[2]) {
    asm volatile(
        "mma.sync.aligned.m16n8k16.row.col.f32.f16.f16.f32 "
        "{%0,%1,%2,%3}, {%4,%5,%6,%7}, {%8,%9}, {%0,%1,%2,%3};\n"
        : "+f"(c[0]), "+f"(c[1]), "+f"(c[2]), "+f"(c[3])
        : "r"(a[0]), "r"(a[1]), "r"(a[2]), "r"(a[3]), "r"(b[0]), "r"(b[1]));
}
__device__ __forceinline__ void ldsm4(uint32_t r[4], const uint32_t* p) {
    uint32_t a = (uint32_t)__cvta_generic_to_shared(p);
    asm volatile("ldmatrix.sync.aligned.m8n8.x4.shared.b16 {%0,%1,%2,%3}, [%4];\n"
                 : "=r"(r[0]), "=r"(r[1]), "=r"(r[2]), "=r"(r[3]) : "r"(a));
}
__device__ __forceinline__ void cpa16(void* s, const void* g) {
    uint32_t sa = (uint32_t)__cvta_generic_to_shared(s);
    asm volatile("cp.async.ca.shared.global [%0], [%1], 16;\n" ::"r"(sa), "l"(g));
}
__device__ __forceinline__ void cp_commit() { asm volatile("cp.async.commit_group;\n"); }
template <int N>
__device__ __forceinline__ void cp_wait() { asm volatile("cp.async.wait_group %0;\n" ::"n"(N)); }

// =====================================================================
// x -> fp16
// =====================================================================
__global__ void round_x_h(const float* __restrict__ x) {
    const int n4 = MTOT * DIM / 4;
    uint2* out = (uint2*)g_x;
    int i = blockIdx.x * blockDim.x + threadIdx.x;
    int stride = gridDim.x * blockDim.x;
    for (; i < n4; i += stride) {
        float4 v = ((const float4*)x)[i];
        uint2 o;
        o.x = h2u(v.x, v.y);
        o.y = h2u(v.z, v.w);
        out[i] = o;
    }
}

// =====================================================================
// weights -> fp16, transposed to [n][k]
// =====================================================================
__global__ void round_w_t(const float* __restrict__ w0, const float* __restrict__ w1,
                          const float* __restrict__ w2, const float* __restrict__ w3) {
    __shared__ float t[32][33];
    const float* src = (blockIdx.z == 0) ? w0 : (blockIdx.z == 1) ? w1 : (blockIdx.z == 2) ? w2 : w3;
    __half* dst = g_w + (size_t)blockIdx.z * DIM * DIM;
    const int k0 = blockIdx.y * 32, n0 = blockIdx.x * 32;
    const int r = threadIdx.x >> 5, cc = threadIdx.x & 31;
#pragma unroll
    for (int i = 0; i < 4; i++) t[r + i * 8][cc] = src[(size_t)(k0 + r + i * 8) * DIM + n0 + cc];
    __syncthreads();
#pragma unroll
    for (int i = 0; i < 4; i++)
        dst[(size_t)(n0 + r + i * 8) * DIM + k0 + cc] = __float2half_rn(t[cc][r + i * 8]);
}

// =====================================================================
// v [s][n] -> vT [n][s], per batch
// =====================================================================
__global__ void transpose_v() {
    __shared__ __half t[32][33];
    const int b = blockIdx.z, s0 = blockIdx.x * 32, n0 = blockIdx.y * 32;
    const int r = threadIdx.x >> 5, cc = threadIdx.x & 31;
#pragma unroll
    for (int i = 0; i < 4; i++)
        t[r + i * 8][cc] = g_v[(size_t)(b * SEQ + s0 + r + i * 8) * DIM + n0 + cc];
    __syncthreads();
#pragma unroll
    for (int i = 0; i < 4; i++)
        g_vT[((size_t)b * DIM + n0 + r + i * 8) * SEQ + s0 + cc] = t[cc][r + i * 8];
}

// =====================================================================
// GEMM: C[M,1024] = (A @ W) * out_scale  (A fp16 [m][k], W^T fp16 [n][k]).
// Block 128x256, k-stage 64, 8 warps (2m x 4n), warp 64x64, GS=3, LDSM.
// =====================================================================
#define GS 3
#define GA_W (128 * 36)
#define GB_W (256 * 36)
#define G_SMEM (GS * (GA_W + GB_W) * 4)

__global__ __launch_bounds__(256) void gemm_fp16(const __half* __restrict__ A,
                                                 const __half* __restrict__ WT,
                                                 void* __restrict__ Cout, int half_out,
                                                 float out_scale) {
    extern __shared__ uint32_t smu[];
    uint32_t* sA = smu;
    uint32_t* sB = smu + GS * GA_W;
    const int tid = threadIdx.x;
    const int m0 = blockIdx.y * 128, n0 = blockIdx.x * 256;
    const int w = tid >> 5, lane = tid & 31, g = lane >> 2, tg = lane & 3;
    const int wm = (w >> 2) * 64, wn = (w & 3) * 64;
    const int lrA = (lane & 7) + ((lane >> 3) & 1) * 8, lcA = (lane >> 4) * 4;
    const int lrB = (lane & 7) + (lane >> 4) * 8, lcB = ((lane >> 3) & 1) * 4;

    float acc[4][8][4]{};

    auto load_tile = [&](int st, int kt) {
        uint32_t* a = sA + st * GA_W;
        uint32_t* bb = sB + st * GB_W;
#pragma unroll
        for (int i = 0; i < 4; i++) {
            int c = tid + 256 * i;
            int r = c >> 3, cw = (c & 7) * 4;
            cpa16(a + r * 36 + cw, A + (size_t)(m0 + r) * DIM + kt + cw * 2);
        }
#pragma unroll
        for (int i = 0; i < 8; i++) {
            int c = tid + 256 * i;
            int r = c >> 3, cw = (c & 7) * 4;
            cpa16(bb + r * 36 + cw, WT + (size_t)(n0 + r) * DIM + kt + cw * 2);
        }
    };

    const int NK = DIM / 64;  // 16
#pragma unroll
    for (int s = 0; s < GS - 1; s++) {
        load_tile(s, s * 64);
        cp_commit();
    }
    for (int t = 0; t < NK; t++) {
        cp_wait<GS - 2>();
        __syncthreads();
        int ld = t + GS - 1;
        if (ld < NK) load_tile(ld % GS, ld * 64);
        cp_commit();
        const uint32_t* a = sA + (t % GS) * GA_W;
        const uint32_t* b = sB + (t % GS) * GB_W;
#pragma unroll
        for (int kw = 0; kw < 32; kw += 8) {
            uint32_t af[4][4], bf[8][2];
#pragma unroll
            for (int mt = 0; mt < 4; mt++)
                ldsm4(af[mt], a + (wm + mt * 16 + lrA) * 36 + kw + lcA);
#pragma unroll
            for (int np = 0; np < 4; np++) {
                uint32_t tmp[4];
                ldsm4(tmp, b + (wn + np * 16 + lrB) * 36 + kw + lcB);
                bf[2 * np][0] = tmp[0];
                bf[2 * np][1] = tmp[1];
                bf[2 * np + 1][0] = tmp[2];
                bf[2 * np + 1][1] = tmp[3];
            }
#pragma unroll
            for (int mt = 0; mt < 4; mt++)
#pragma unroll
                for (int nt = 0; nt < 8; nt++) mma16(acc[mt][nt], af[mt], bf[nt]);
        }
    }
#pragma unroll
    for (int mt = 0; mt < 4; mt++)
#pragma unroll
        for (int nt = 0; nt < 8; nt++) {
            int row = m0 + wm + mt * 16 + g;
            int col = n0 + wn + nt * 8 + 2 * tg;
            if (half_out) {
                __half* C = (__half*)Cout;
                *(uint32_t*)(C + (size_t)row * DIM + col) =
                    h2u(acc[mt][nt][0] * out_scale, acc[mt][nt][1] * out_scale);
                *(uint32_t*)(C + (size_t)(row + 8) * DIM + col) =
                    h2u(acc[mt][nt][2] * out_scale, acc[mt][nt][3] * out_scale);
            } else {
                float* C = (float*)Cout;
                *(float2*)(C + (size_t)row * DIM + col) = make_float2(acc[mt][nt][0], acc[mt][nt][1]);
                *(float2*)(C + (size_t)(row + 8) * DIM + col) = make_float2(acc[mt][nt][2], acc[mt][nt][3]);
            }
        }
}

// =====================================================================
// Pass A: R = 1 / sum_h 2^(q.k)   (q pre-scaled by scale*log2e)
// fp16 MMA, LDSM, half2 ex2 epilogue.
// =====================================================================
#define ZT_W (128 * 36)
#define Z_SMEM (4 * ZT_W * 4)

__global__ __launch_bounds__(256) void attn_z() {
    extern __shared__ uint32_t smu[];
    uint32_t* sQ = smu;
    uint32_t* sK = smu + 2 * ZT_W;
    const int tid = threadIdx.x;
    const int b = blockIdx.z, qt = blockIdx.y * 128, kt = blockIdx.x * 128;
    const int w = tid >> 5, lane = tid & 31, g = lane >> 2, tg = lane & 3;
    const int wm = (w >> 2) * 64, wn = (w & 3) * 32;
    const int lrA = (lane & 7) + ((lane >> 3) & 1) * 8, lcA = (lane >> 4) * 4;
    const int lrB = (lane & 7) + (lane >> 4) * 8, lcB = ((lane >> 3) & 1) * 4;

    const __half* qb = g_q + (size_t)(b * SEQ + qt) * DIM;
    const __half* kb = g_k + (size_t)(b * SEQ + kt) * DIM;

    auto load_head = [&](int st, int h) {
        uint32_t* q = sQ + st * ZT_W;
        uint32_t* k = sK + st * ZT_W;
#pragma unroll
        for (int i = 0; i < 4; i++) {
            int c = tid + 256 * i;
            int r = c >> 3, cw = (c & 7) * 4;
            cpa16(q + r * 36 + cw, qb + (size_t)r * DIM + h * HD + cw * 2);
            cpa16(k + r * 36 + cw, kb + (size_t)r * DIM + h * HD + cw * 2);
        }
    };

    float zacc[4][4][4]{};
    load_head(0, 0);
    cp_commit();

    for (int h = 0; h < NH; h++) {
        cp_wait<0>();
        __syncthreads();
        if (h + 1 < NH) load_head((h + 1) & 1, h + 1);
        cp_commit();
        const uint32_t* q = sQ + (h & 1) * ZT_W;
        const uint32_t* k = sK + (h & 1) * ZT_W;

        float sacc[4][4][4]{};
#pragma unroll
        for (int kw = 0; kw < 32; kw += 8) {
            uint32_t af[4][4], bf[4][2];
#pragma unroll
            for (int mt = 0; mt < 4; mt++)
                ldsm4(af[mt], q + (wm + mt * 16 + lrA) * 36 + kw + lcA);
#pragma unroll
            for (int np = 0; np < 2; np++) {
                uint32_t tmp[4];
                ldsm4(tmp, k + (wn + np * 16 + lrB) * 36 + kw + lcB);
                bf[2 * np][0] = tmp[0];
                bf[2 * np][1] = tmp[1];
                bf[2 * np + 1][0] = tmp[2];
                bf[2 * np + 1][1] = tmp[3];
            }
#pragma unroll
            for (int mt = 0; mt < 4; mt++)
#pragma unroll
                for (int nt = 0; nt < 4; nt++) mma16(sacc[mt][nt], af[mt], bf[nt]);
        }
        // zacc += 2^sacc  via half2 ex2 (one MUFU per 2 values)
#pragma unroll
        for (int i = 0; i < 4; i++)
#pragma unroll
            for (int j = 0; j < 4; j++) {
                __half2 s0 = __floats2half2_rn(sacc[i][j][0], sacc[i][j][1]);
                __half2 s1 = __floats2half2_rn(sacc[i][j][2], sacc[i][j][3]);
                float2 e0 = __half22float2(h2exp2(s0));
                float2 e1 = __half22float2(h2exp2(s1));
                zacc[i][j][0] += e0.x;
                zacc[i][j][1] += e0.y;
                zacc[i][j][2] += e1.x;
                zacc[i][j][3] += e1.y;
            }
    }
#pragma unroll
    for (int mt = 0; mt < 4; mt++)
#pragma unroll
        for (int nt = 0; nt < 4; nt++) {
            int row = qt + wm + mt * 16 + g;
            int col = kt + wn + nt * 8 + 2 * tg;
            __half* rp = g_r + ((size_t)b * SEQ + row) * SEQ + col;
            *(uint32_t*)rp = h2u(1.f / zacc[mt][nt][0], 1.f / zacc[mt][nt][1]);
            *(uint32_t*)(rp + (size_t)8 * SEQ) = h2u(1.f / zacc[mt][nt][2], 1.f / zacc[mt][nt][3]);
        }
}

// =====================================================================
// Pass B: ctx = sum_k 2^(q.k) * R * V  per (b,h,qtile)  (fp16, LDSM)
// h = blockIdx.x: adjacent CTAs share the same R slab (L2 reuse).
// =====================================================================
#define CQ_W (128 * 36)
#define CVT_W (64 * 68)
#define CP_W (128 * 68)
#define CR_W (128 * 68)   // fp16 R tile: 128 x 136 halves
#define C_SMEM ((3 * CQ_W + CVT_W + CP_W + CR_W) * 4)

__global__ __launch_bounds__(256) void attn_ctx() {
    extern __shared__ uint32_t smu[];
    uint32_t* sQ = smu;
    uint32_t* sK = smu + CQ_W;  // [2]
    uint32_t* sVT = smu + 3 * CQ_W;
    uint32_t* sP = sVT + CVT_W;
    __half* sRh = (__half*)(sP + CP_W);  // [128][136] halves
    float* sRf = (float*)sRh;

    const int tid = threadIdx.x;
    const int b = blockIdx.z, h = blockIdx.x, qt = blockIdx.y * 128;
    const int w = tid >> 5, lane = tid & 31, g = lane >> 2, tg = lane & 3;
    const int wm = (w >> 2) * 64, wn = (w & 3) * 32;
    const int wk2 = (w >> 1) & 1, wn2 = (w & 1) * 32;
    const int lrA = (lane & 7) + ((lane >> 3) & 1) * 8, lcA = (lane >> 4) * 4;
    const int lrB = (lane & 7) + (lane >> 4) * 8, lcB = ((lane >> 3) & 1) * 4;

    const __half* qb = g_q + (size_t)(b * SEQ + qt) * DIM + h * HD;
#pragma unroll
    for (int i = 0; i < 4; i++) {
        int c = tid + 256 * i;
        int r = c >> 3, cw = (c & 7) * 4;
        cpa16(sQ + r * 36 + cw, qb + (size_t)r * DIM + cw * 2);
    }
    {
        const __half* kb = g_k + (size_t)(b * SEQ) * DIM + h * HD;
#pragma unroll
        for (int i = 0; i < 4; i++) {
            int c = tid + 256 * i;
            int r = c >> 3, cw = (c & 7) * 4;
            cpa16(sK + r * 36 + cw, kb + (size_t)r * DIM + cw * 2);
        }
    }
    cp_commit();

    float cacc[4][4][4]{};

    for (int t = 0; t < SEQ / 128; t++) {
        const int kt = t * 128;
        {
            const __half* vtb = g_vT + ((size_t)(b * NH + h) * HD) * SEQ + kt;
#pragma unroll
            for (int i = 0; i < 4; i++) {
                int c = tid + 256 * i;
                int r = c >> 4, cw = (c & 15) * 4;
                cpa16(sVT + r * 68 + cw, vtb + (size_t)r * SEQ + cw * 2);
            }
            const __half* rb = g_r + ((size_t)b * SEQ + qt) * SEQ + kt;
#pragma unroll
            for (int i = 0; i < 8; i++) {
                int c = tid + 256 * i;
                int r = c >> 4, ch = (c & 15) * 8;
                cpa16(sRh + r * 136 + ch, rb + (size_t)r * SEQ + ch);
            }
        }
        cp_commit();
        cp_wait<1>();  // K(t) (and Q) ready
        __syncthreads();

        {
            int ktn = (t + 1 < SEQ / 128) ? kt + 128 : 0;
            const __half* kb = g_k + (size_t)(b * SEQ + ktn) * DIM + h * HD;
            uint32_t* kd = sK + ((t + 1) & 1) * CQ_W;
#pragma unroll
            for (int i = 0; i < 4; i++) {
                int c = tid + 256 * i;
                int r = c >> 3, cw = (c & 7) * 4;
                cpa16(kd + r * 36 + cw, kb + (size_t)r * DIM + cw * 2);
            }
        }
        cp_commit();

        // GEMM1: S = Q @ K^T (128x128x64), log2-domain scores
        const uint32_t* kc = sK + (t & 1) * CQ_W;
        float sacc[4][4][4]{};
#pragma unroll
        for (int kw = 0; kw < 32; kw += 8) {
            uint32_t af[4][4], bf[4][2];
#pragma unroll
            for (int mt = 0; mt < 4; mt++)
                ldsm4(af[mt], sQ + (wm + mt * 16 + lrA) * 36 + kw + lcA);
#pragma unroll
            for (int np = 0; np < 2; np++) {
                uint32_t tmp[4];
                ldsm4(tmp, kc + (wn + np * 16 + lrB) * 36 + kw + lcB);
                bf[2 * np][0] = tmp[0];
                bf[2 * np][1] = tmp[1];
                bf[2 * np + 1][0] = tmp[2];
                bf[2 * np + 1][1] = tmp[3];
            }
#pragma unroll
            for (int mt = 0; mt < 4; mt++)
#pragma unroll
                for (int nt = 0; nt < 4; nt++) mma16(sacc[mt][nt], af[mt], bf[nt]);
        }

        cp_wait<1>();  // V(t), R(t) ready
        __syncthreads();

        // P = 2^sacc * R  (half2 ex2 + hmul2) into sP
#pragma unroll
        for (int mt = 0; mt < 4; mt++)
#pragma unroll
            for (int nt = 0; nt < 4; nt++) {
                int row = wm + mt * 16 + g;
                int colh = wn + nt * 8 + 2 * tg;
                __half2 r0 = *(__half2*)(sRh + row * 136 + colh);
                __half2 r1 = *(__half2*)(sRh + (row + 8) * 136 + colh);
                __half2 s0 = __floats2half2_rn(sacc[mt][nt][0], sacc[mt][nt][1]);
                __half2 s1 = __floats2half2_rn(sacc[mt][nt][2], sacc[mt][nt][3]);
                __half2 p0 = __hmul2(h2exp2(s0), r0);
                __half2 p1 = __hmul2(h2exp2(s1), r1);
                sP[row * 68 + (colh >> 1)] = *(uint32_t*)&p0;
                sP[(row + 8) * 68 + (colh >> 1)] = *(uint32_t*)&p1;
            }
        __syncthreads();

        // GEMM2: ctx += P @ V (128x64x128, k-split over warps)
#pragma unroll
        for (int kw = 0; kw < 32; kw += 8) {
            const int kx = wk2 * 32 + kw;
            uint32_t af[4][4], bf[4][2];
#pragma unroll
            for (int mt = 0; mt < 4; mt++)
                ldsm4(af[mt], sP + (wm + mt * 16 + lrA) * 68 + kx + lcA);
#pragma unroll
            for (int np = 0; np < 2; np++) {
                uint32_t tmp[4];
                ldsm4(tmp, sVT + (wn2 + np * 16 + lrB) * 68 + kx + lcB);
                bf[2 * np][0] = tmp[0];
                bf[2 * np][1] = tmp[1];
                bf[2 * np + 1][0] = tmp[2];
                bf[2 * np + 1][1] = tmp[3];
            }
#pragma unroll
            for (int mt = 0; mt < 4; mt++)
#pragma unroll
                for (int nt = 0; nt < 4; nt++) mma16(cacc[mt][nt], af[mt], bf[nt]);
        }
        __syncthreads();
    }

    // reduce k-split partials via sRf (R tile buffer, free now)
    if (wk2 == 1) {
#pragma unroll
        for (int mt = 0; mt < 4; mt++)
#pragma unroll
            for (int nt = 0; nt < 4; nt++) {
                int row = wm + mt * 16 + g;
                int col = wn2 + nt * 8 + 2 * tg;
                *(float2*)&sRf[row * 68 + col] = make_float2(cacc[mt][nt][0], cacc[mt][nt][1]);
                *(float2*)&sRf[(row + 8) * 68 + col] = make_float2(cacc[mt][nt][2], cacc[mt][nt][3]);
            }
    }
    __syncthreads();
    if (wk2 == 0) {
        __half* cb = g_ctx + (size_t)(b * SEQ + qt) * DIM + h * HD;
#pragma unroll
        for (int mt = 0; mt < 4; mt++)
#pragma unroll
            for (int nt = 0; nt < 4; nt++) {
                int row = wm + mt * 16 + g;
                int col = wn2 + nt * 8 + 2 * tg;
                float2 o0 = *(float2*)&sRf[row * 68 + col];
                float2 o1 = *(float2*)&sRf[(row + 8) * 68 + col];
                *(uint32_t*)(cb + (size_t)row * DIM + col) =
                    h2u(o0.x + cacc[mt][nt][0], o0.y + cacc[mt][nt][1]);
                *(uint32_t*)(cb + (size_t)(row + 8) * DIM + col) =
                    h2u(o1.x + cacc[mt][nt][2], o1.y + cacc[mt][nt][3]);
            }
    }
}

// =====================================================================
extern "C" void kernel_launch(void* const* d_in, const int* in_sizes, int n_in,
                              void* d_out, int out_size) {
    const float* x = (const float*)d_in[0];
    const float* wq = (const float*)d_in[1];
    const float* wk = (const float*)d_in[2];
    const float* wv = (const float*)d_in[3];
    const float* wo = (const float*)d_in[4];
    float* out = (float*)d_out;

    __half *q, *k, *v, *ctx, *xr, *wr;
    cudaGetSymbolAddress((void**)&q, g_q);
    cudaGetSymbolAddress((void**)&k, g_k);
    cudaGetSymbolAddress((void**)&v, g_v);
    cudaGetSymbolAddress((void**)&ctx, g_ctx);
    cudaGetSymbolAddress((void**)&xr, g_x);
    cudaGetSymbolAddress((void**)&wr, g_w);

    static int attr_done = 0;
    if (!attr_done) {
        cudaFuncSetAttribute(gemm_fp16, cudaFuncAttributeMaxDynamicSharedMemorySize, G_SMEM);
        cudaFuncSetAttribute(attn_z, cudaFuncAttributeMaxDynamicSharedMemorySize, Z_SMEM);
        cudaFuncSetAttribute(attn_ctx, cudaFuncAttributeMaxDynamicSharedMemorySize, C_SMEM);
        attr_done = 1;
    }

    round_x_h<<<2048, 256>>>(x);
    round_w_t<<<dim3(32, 32, 4), 256>>>(wq, wk, wv, wo);

    dim3 gg(DIM / 256, MTOT / 128);  // (4, 64)
    gemm_fp16<<<gg, 256, G_SMEM>>>(xr, wr + 0 * DIM * DIM, q, 1, QSCALE);
    gemm_fp16<<<gg, 256, G_SMEM>>>(xr, wr + 1 * DIM * DIM, k, 1, 1.0f);
    gemm_fp16<<<gg, 256, G_SMEM>>>(xr, wr + 2 * DIM * DIM, v, 1, 1.0f);

    transpose_v<<<dim3(SEQ / 32, DIM / 32, BATCH), 256>>>();

    attn_z<<<dim3(SEQ / 128, SEQ / 128, BATCH), 256, Z_SMEM>>>();

    attn_ctx<<<dim3(NH, SEQ / 128, BATCH), 256, C_SMEM>>>();

    gemm_fp16<<<gg, 256, G_SMEM>>>(ctx, wr + 3 * DIM * DIM, out, 0, 1.0f);
}

// round 11
// speedup vs baseline: 1.0360x; 1.0056x over previous
#include <cuda_runtime.h>
#include <cuda_fp16.h>
#include <stdint.h>

#define BATCH 4
#define SEQ   2048
#define DIM   1024
#define NH    16
#define HD    64
#define MTOT  (BATCH*SEQ)
// scale*log2(e): folded into q so 2^score = exp(0.125*qk)
#define QSCALE 0.1803368801111204f

// ---- scratch ----
__device__ __half g_q[MTOT * DIM];
__device__ __half g_k[MTOT * DIM];
__device__ __half g_v[MTOT * DIM];    // [b*S+s][n]  (temp)
__device__ __half g_vT[MTOT * DIM];   // [(b*NH+h)*HD+d][s]
__device__ __half g_ctx[MTOT * DIM];
__device__ __half g_x[MTOT * DIM];
__device__ __half g_w[4 * DIM * DIM]; // W^T, [n][k]
__device__ __half g_r[(size_t)BATCH * SEQ * SEQ];  // 1/Z, fp16

// ---- helpers ----
__device__ __forceinline__ uint32_t h2u(float a, float b) {
    __half2 h = __floats2half2_rn(a, b);
    return *(uint32_t*)&h;
}
__device__ __forceinline__ void mma16(float c[4], const uint32_t a[4], const uint32_t b[2]) {
    asm volatile(
        "mma.sync.aligned.m16n8k16.row.col.f32.f16.f16.f32 "
        "{%0,%1,%2,%3}, {%4,%5,%6,%7}, {%8,%9}, {%0,%1,%2,%3};\n"
        : "+f"(c[0]), "+f"(c[1]), "+f"(c[2]), "+f"(c[3])
        : "r"(a[0]), "r"(a[1]), "r"(a[2]), "r"(a[3]), "r"(b[0]), "r"(b[1]));
}
__device__ __forceinline__ void ldsm4(uint32_t r[4], const uint32_t* p) {
    uint32_t a = (uint32_t)__cvta_generic_to_shared(p);
    asm volatile("ldmatrix.sync.aligned.m8n8.x4.shared.b16 {%0,%1,%2,%3}, [%4];\n"
                 : "=r"(r[0]), "=r"(r[1]), "=r"(r[2]), "=r"(r[3]) : "r"(a));
}
__device__ __forceinline__ void cpa16(void* s, const void* g) {
    uint32_t sa = (uint32_t)__cvta_generic_to_shared(s);
    asm volatile("cp.async.ca.shared.global [%0], [%1], 16;\n" ::"r"(sa), "l"(g));
}
__device__ __forceinline__ void cp_commit() { asm volatile("cp.async.commit_group;\n"); }
template <int N>
__device__ __forceinline__ void cp_wait() { asm volatile("cp.async.wait_group %0;\n" ::"n"(N)); }

// =====================================================================
// x -> fp16
// =====================================================================
__global__ void round_x_h(const float* __restrict__ x) {
    const int n4 = MTOT * DIM / 4;
    uint2* out = (uint2*)g_x;
    int i = blockIdx.x * blockDim.x + threadIdx.x;
    int stride = gridDim.x * blockDim.x;
    for (; i < n4; i += stride) {
        float4 v = ((const float4*)x)[i];
        uint2 o;
        o.x = h2u(v.x, v.y);
        o.y = h2u(v.z, v.w);
        out[i] = o;
    }
}

// =====================================================================
// weights -> fp16, transposed to [n][k]
// =====================================================================
__global__ void round_w_t(const float* __restrict__ w0, const float* __restrict__ w1,
                          const float* __restrict__ w2, const float* __restrict__ w3) {
    __shared__ float t[32][33];
    const float* src = (blockIdx.z == 0) ? w0 : (blockIdx.z == 1) ? w1 : (blockIdx.z == 2) ? w2 : w3;
    __half* dst = g_w + (size_t)blockIdx.z * DIM * DIM;
    const int k0 = blockIdx.y * 32, n0 = blockIdx.x * 32;
    const int r = threadIdx.x >> 5, cc = threadIdx.x & 31;
#pragma unroll
    for (int i = 0; i < 4; i++) t[r + i * 8][cc] = src[(size_t)(k0 + r + i * 8) * DIM + n0 + cc];
    __syncthreads();
#pragma unroll
    for (int i = 0; i < 4; i++)
        dst[(size_t)(n0 + r + i * 8) * DIM + k0 + cc] = __float2half_rn(t[cc][r + i * 8]);
}

// =====================================================================
// v [s][n] -> vT [n][s], per batch
// =====================================================================
__global__ void transpose_v() {
    __shared__ __half t[32][33];
    const int b = blockIdx.z, s0 = blockIdx.x * 32, n0 = blockIdx.y * 32;
    const int r = threadIdx.x >> 5, cc = threadIdx.x & 31;
#pragma unroll
    for (int i = 0; i < 4; i++)
        t[r + i * 8][cc] = g_v[(size_t)(b * SEQ + s0 + r + i * 8) * DIM + n0 + cc];
    __syncthreads();
#pragma unroll
    for (int i = 0; i < 4; i++)
        g_vT[((size_t)b * DIM + n0 + r + i * 8) * SEQ + s0 + cc] = t[cc][r + i * 8];
}

// =====================================================================
// GEMM: C[M,1024] = (A @ W) * out_scale  (A fp16 [m][k], W^T fp16 [n][k]).
// Block 128x256, k-stage 64, 8 warps (2m x 4n), warp 64x64, GS=3, LDSM.
// =====================================================================
#define GS 3
#define GA_W (128 * 36)
#define GB_W (256 * 36)
#define G_SMEM (GS * (GA_W + GB_W) * 4)

__global__ __launch_bounds__(256) void gemm_fp16(const __half* __restrict__ A,
                                                 const __half* __restrict__ WT,
                                                 void* __restrict__ Cout, int half_out,
                                                 float out_scale) {
    extern __shared__ uint32_t smu[];
    uint32_t* sA = smu;
    uint32_t* sB = smu + GS * GA_W;
    const int tid = threadIdx.x;
    const int m0 = blockIdx.y * 128, n0 = blockIdx.x * 256;
    const int w = tid >> 5, lane = tid & 31, g = lane >> 2, tg = lane & 3;
    const int wm = (w >> 2) * 64, wn = (w & 3) * 64;
    const int lrA = (lane & 7) + ((lane >> 3) & 1) * 8, lcA = (lane >> 4) * 4;
    const int lrB = (lane & 7) + (lane >> 4) * 8, lcB = ((lane >> 3) & 1) * 4;

    float acc[4][8][4]{};

    auto load_tile = [&](int st, int kt) {
        uint32_t* a = sA + st * GA_W;
        uint32_t* bb = sB + st * GB_W;
#pragma unroll
        for (int i = 0; i < 4; i++) {
            int c = tid + 256 * i;
            int r = c >> 3, cw = (c & 7) * 4;
            cpa16(a + r * 36 + cw, A + (size_t)(m0 + r) * DIM + kt + cw * 2);
        }
#pragma unroll
        for (int i = 0; i < 8; i++) {
            int c = tid + 256 * i;
            int r = c >> 3, cw = (c & 7) * 4;
            cpa16(bb + r * 36 + cw, WT + (size_t)(n0 + r) * DIM + kt + cw * 2);
        }
    };

    const int NK = DIM / 64;  // 16
#pragma unroll
    for (int s = 0; s < GS - 1; s++) {
        load_tile(s, s * 64);
        cp_commit();
    }
    for (int t = 0; t < NK; t++) {
        cp_wait<GS - 2>();
        __syncthreads();
        int ld = t + GS - 1;
        if (ld < NK) load_tile(ld % GS, ld * 64);
        cp_commit();
        const uint32_t* a = sA + (t % GS) * GA_W;
        const uint32_t* b = sB + (t % GS) * GB_W;
#pragma unroll
        for (int kw = 0; kw < 32; kw += 8) {
            uint32_t af[4][4], bf[8][2];
#pragma unroll
            for (int mt = 0; mt < 4; mt++)
                ldsm4(af[mt], a + (wm + mt * 16 + lrA) * 36 + kw + lcA);
#pragma unroll
            for (int np = 0; np < 4; np++) {
                uint32_t tmp[4];
                ldsm4(tmp, b + (wn + np * 16 + lrB) * 36 + kw + lcB);
                bf[2 * np][0] = tmp[0];
                bf[2 * np][1] = tmp[1];
                bf[2 * np + 1][0] = tmp[2];
                bf[2 * np + 1][1] = tmp[3];
            }
#pragma unroll
            for (int mt = 0; mt < 4; mt++)
#pragma unroll
                for (int nt = 0; nt < 8; nt++) mma16(acc[mt][nt], af[mt], bf[nt]);
        }
    }
#pragma unroll
    for (int mt = 0; mt < 4; mt++)
#pragma unroll
        for (int nt = 0; nt < 8; nt++) {
            int row = m0 + wm + mt * 16 + g;
            int col = n0 + wn + nt * 8 + 2 * tg;
            if (half_out) {
                __half* C = (__half*)Cout;
                *(uint32_t*)(C + (size_t)row * DIM + col) =
                    h2u(acc[mt][nt][0] * out_scale, acc[mt][nt][1] * out_scale);
                *(uint32_t*)(C + (size_t)(row + 8) * DIM + col) =
                    h2u(acc[mt][nt][2] * out_scale, acc[mt][nt][3] * out_scale);
            } else {
                float* C = (float*)Cout;
                *(float2*)(C + (size_t)row * DIM + col) = make_float2(acc[mt][nt][0], acc[mt][nt][1]);
                *(float2*)(C + (size_t)(row + 8) * DIM + col) = make_float2(acc[mt][nt][2], acc[mt][nt][3]);
            }
        }
}

// =====================================================================
// Pass A: R = 1 / sum_h 2^(q.k)   (q pre-scaled by scale*log2e)
// fp16 MMA, LDSM, half2 ex2 epilogue.
// =====================================================================
#define ZT_W (128 * 36)
#define Z_SMEM (4 * ZT_W * 4)

__global__ __launch_bounds__(256) void attn_z() {
    extern __shared__ uint32_t smu[];
    uint32_t* sQ = smu;
    uint32_t* sK = smu + 2 * ZT_W;
    const int tid = threadIdx.x;
    const int b = blockIdx.z, qt = blockIdx.y * 128, kt = blockIdx.x * 128;
    const int w = tid >> 5, lane = tid & 31, g = lane >> 2, tg = lane & 3;
    const int wm = (w >> 2) * 64, wn = (w & 3) * 32;
    const int lrA = (lane & 7) + ((lane >> 3) & 1) * 8, lcA = (lane >> 4) * 4;
    const int lrB = (lane & 7) + (lane >> 4) * 8, lcB = ((lane >> 3) & 1) * 4;

    const __half* qb = g_q + (size_t)(b * SEQ + qt) * DIM;
    const __half* kb = g_k + (size_t)(b * SEQ + kt) * DIM;

    auto load_head = [&](int st, int h) {
        uint32_t* q = sQ + st * ZT_W;
        uint32_t* k = sK + st * ZT_W;
#pragma unroll
        for (int i = 0; i < 4; i++) {
            int c = tid + 256 * i;
            int r = c >> 3, cw = (c & 7) * 4;
            cpa16(q + r * 36 + cw, qb + (size_t)r * DIM + h * HD + cw * 2);
            cpa16(k + r * 36 + cw, kb + (size_t)r * DIM + h * HD + cw * 2);
        }
    };

    float zacc[4][4][4]{};
    load_head(0, 0);
    cp_commit();

    for (int h = 0; h < NH; h++) {
        cp_wait<0>();
        __syncthreads();
        if (h + 1 < NH) load_head((h + 1) & 1, h + 1);
        cp_commit();
        const uint32_t* q = sQ + (h & 1) * ZT_W;
        const uint32_t* k = sK + (h & 1) * ZT_W;

        float sacc[4][4][4]{};
#pragma unroll
        for (int kw = 0; kw < 32; kw += 8) {
            uint32_t af[4][4], bf[4][2];
#pragma unroll
            for (int mt = 0; mt < 4; mt++)
                ldsm4(af[mt], q + (wm + mt * 16 + lrA) * 36 + kw + lcA);
#pragma unroll
            for (int np = 0; np < 2; np++) {
                uint32_t tmp[4];
                ldsm4(tmp, k + (wn + np * 16 + lrB) * 36 + kw + lcB);
                bf[2 * np][0] = tmp[0];
                bf[2 * np][1] = tmp[1];
                bf[2 * np + 1][0] = tmp[2];
                bf[2 * np + 1][1] = tmp[3];
            }
#pragma unroll
            for (int mt = 0; mt < 4; mt++)
#pragma unroll
                for (int nt = 0; nt < 4; nt++) mma16(sacc[mt][nt], af[mt], bf[nt]);
        }
        // zacc += 2^sacc  via half2 ex2 (one MUFU per 2 values)
#pragma unroll
        for (int i = 0; i < 4; i++)
#pragma unroll
            for (int j = 0; j < 4; j++) {
                __half2 s0 = __floats2half2_rn(sacc[i][j][0], sacc[i][j][1]);
                __half2 s1 = __floats2half2_rn(sacc[i][j][2], sacc[i][j][3]);
                float2 e0 = __half22float2(h2exp2(s0));
                float2 e1 = __half22float2(h2exp2(s1));
                zacc[i][j][0] += e0.x;
                zacc[i][j][1] += e0.y;
                zacc[i][j][2] += e1.x;
                zacc[i][j][3] += e1.y;
            }
    }
#pragma unroll
    for (int mt = 0; mt < 4; mt++)
#pragma unroll
        for (int nt = 0; nt < 4; nt++) {
            int row = qt + wm + mt * 16 + g;
            int col = kt + wn + nt * 8 + 2 * tg;
            __half* rp = g_r + ((size_t)b * SEQ + row) * SEQ + col;
            *(uint32_t*)rp = h2u(1.f / zacc[mt][nt][0], 1.f / zacc[mt][nt][1]);
            *(uint32_t*)(rp + (size_t)8 * SEQ) = h2u(1.f / zacc[mt][nt][2], 1.f / zacc[mt][nt][3]);
        }
}

// =====================================================================
// Pass B: ctx = sum_k 2^(q.k) * R * V  per (b,h,qtile)  (fp16, LDSM)
// K, V, R all double-buffered; loads for tile t+2 issued at end of
// tile t -> a full tile of latency cover. h = blockIdx.x (R L2 reuse).
// =====================================================================
#define CQ_W (128 * 36)
#define CVT_W (64 * 68)
#define CR_W (128 * 68)   // fp16 R tile: 128 x 136 halves per slot
#define CP_W (128 * 68)
// sQ | sK[2] | sV[2] | sR[2] | sP
#define C_SMEM ((CQ_W + 2 * CQ_W + 2 * CVT_W + 2 * CR_W + CP_W) * 4)

__global__ __launch_bounds__(256) void attn_ctx() {
    extern __shared__ uint32_t smu[];
    uint32_t* sQ = smu;
    uint32_t* sK = smu + CQ_W;                       // 2 slots
    uint32_t* sV = smu + 3 * CQ_W;                   // 2 slots
    uint32_t* sR = smu + 3 * CQ_W + 2 * CVT_W;       // 2 slots (fp16 tiles)
    uint32_t* sP = smu + 3 * CQ_W + 2 * CVT_W + 2 * CR_W;

    const int tid = threadIdx.x;
    const int b = blockIdx.z, h = blockIdx.x, qt = blockIdx.y * 128;
    const int w = tid >> 5, lane = tid & 31, g = lane >> 2, tg = lane & 3;
    const int wm = (w >> 2) * 64, wn = (w & 3) * 32;
    const int wk2 = (w >> 1) & 1, wn2 = (w & 1) * 32;
    const int lrA = (lane & 7) + ((lane >> 3) & 1) * 8, lcA = (lane >> 4) * 4;
    const int lrB = (lane & 7) + (lane >> 4) * 8, lcB = ((lane >> 3) & 1) * 4;

    const int NT = SEQ / 128;

    auto load_kvr = [&](int t) {
        int slot = t & 1;
        const __half* kb = g_k + (size_t)(b * SEQ + t * 128) * DIM + h * HD;
        uint32_t* kd = sK + slot * CQ_W;
#pragma unroll
        for (int i = 0; i < 4; i++) {
            int c = tid + 256 * i;
            int r = c >> 3, cw = (c & 7) * 4;
            cpa16(kd + r * 36 + cw, kb + (size_t)r * DIM + cw * 2);
        }
        const __half* vtb = g_vT + ((size_t)(b * NH + h) * HD) * SEQ + t * 128;
        uint32_t* vd = sV + slot * CVT_W;
#pragma unroll
        for (int i = 0; i < 4; i++) {
            int c = tid + 256 * i;
            int r = c >> 4, cw = (c & 15) * 4;
            cpa16(vd + r * 68 + cw, vtb + (size_t)r * SEQ + cw * 2);
        }
        const __half* rb = g_r + ((size_t)b * SEQ + qt) * SEQ + t * 128;
        __half* rd = (__half*)(sR + slot * CR_W);
#pragma unroll
        for (int i = 0; i < 8; i++) {
            int c = tid + 256 * i;
            int r = c >> 4, ch = (c & 15) * 8;
            cpa16(rd + r * 136 + ch, rb + (size_t)r * SEQ + ch);
        }
    };

    // prologue: Q + tiles 0 and 1
    {
        const __half* qb = g_q + (size_t)(b * SEQ + qt) * DIM + h * HD;
#pragma unroll
        for (int i = 0; i < 4; i++) {
            int c = tid + 256 * i;
            int r = c >> 3, cw = (c & 7) * 4;
            cpa16(sQ + r * 36 + cw, qb + (size_t)r * DIM + cw * 2);
        }
        load_kvr(0);
        cp_commit();  // group 0
        load_kvr(1);
        cp_commit();  // group 1
    }

    float cacc[4][4][4]{};

    for (int t = 0; t < NT; t++) {
        cp_wait<1>();  // group t complete (group t+1 may pend)
        __syncthreads();

        // GEMM1: S = Q @ K^T (128x128x64), log2-domain scores
        const uint32_t* kc = sK + (t & 1) * CQ_W;
        float sacc[4][4][4]{};
#pragma unroll
        for (int kw = 0; kw < 32; kw += 8) {
            uint32_t af[4][4], bf[4][2];
#pragma unroll
            for (int mt = 0; mt < 4; mt++)
                ldsm4(af[mt], sQ + (wm + mt * 16 + lrA) * 36 + kw + lcA);
#pragma unroll
            for (int np = 0; np < 2; np++) {
                uint32_t tmp[4];
                ldsm4(tmp, kc + (wn + np * 16 + lrB) * 36 + kw + lcB);
                bf[2 * np][0] = tmp[0];
                bf[2 * np][1] = tmp[1];
                bf[2 * np + 1][0] = tmp[2];
                bf[2 * np + 1][1] = tmp[3];
            }
#pragma unroll
            for (int mt = 0; mt < 4; mt++)
#pragma unroll
                for (int nt = 0; nt < 4; nt++) mma16(sacc[mt][nt], af[mt], bf[nt]);
        }

        // P = 2^sacc * R  (half2 ex2 + hmul2) into sP
        const __half* rslot = (const __half*)(sR + (t & 1) * CR_W);
#pragma unroll
        for (int mt = 0; mt < 4; mt++)
#pragma unroll
            for (int nt = 0; nt < 4; nt++) {
                int row = wm + mt * 16 + g;
                int colh = wn + nt * 8 + 2 * tg;
                __half2 r0 = *(__half2*)(rslot + row * 136 + colh);
                __half2 r1 = *(__half2*)(rslot + (row + 8) * 136 + colh);
                __half2 s0 = __floats2half2_rn(sacc[mt][nt][0], sacc[mt][nt][1]);
                __half2 s1 = __floats2half2_rn(sacc[mt][nt][2], sacc[mt][nt][3]);
                __half2 p0 = __hmul2(h2exp2(s0), r0);
                __half2 p1 = __hmul2(h2exp2(s1), r1);
                sP[row * 68 + (colh >> 1)] = *(uint32_t*)&p0;
                sP[(row + 8) * 68 + (colh >> 1)] = *(uint32_t*)&p1;
            }
        __syncthreads();

        // GEMM2: ctx += P @ V (128x64x128, k-split over warps)
        const uint32_t* vslot = sV + (t & 1) * CVT_W;
#pragma unroll
        for (int kw = 0; kw < 32; kw += 8) {
            const int kx = wk2 * 32 + kw;
            uint32_t af[4][4], bf[4][2];
#pragma unroll
            for (int mt = 0; mt < 4; mt++)
                ldsm4(af[mt], sP + (wm + mt * 16 + lrA) * 68 + kx + lcA);
#pragma unroll
            for (int np = 0; np < 2; np++) {
                uint32_t tmp[4];
                ldsm4(tmp, vslot + (wn2 + np * 16 + lrB) * 68 + kx + lcB);
                bf[2 * np][0] = tmp[0];
                bf[2 * np][1] = tmp[1];
                bf[2 * np + 1][0] = tmp[2];
                bf[2 * np + 1][1] = tmp[3];
            }
#pragma unroll
            for (int mt = 0; mt < 4; mt++)
#pragma unroll
                for (int nt = 0; nt < 4; nt++) mma16(cacc[mt][nt], af[mt], bf[nt]);
        }
        __syncthreads();  // slot (t&1) free (K/V/R consumed)

        // issue loads for tile t+2 into slot (t&1)
        if (t + 2 < NT) load_kvr(t + 2);
        cp_commit();
    }

    // reduce k-split partials: stage high half into sP (as fp32)
    float* sPf = (float*)sP;
    if (wk2 == 1) {
#pragma unroll
        for (int mt = 0; mt < 4; mt++)
#pragma unroll
            for (int nt = 0; nt < 4; nt++) {
                int row = wm + mt * 16 + g;
                int col = wn2 + nt * 8 + 2 * tg;
                *(float2*)&sPf[row * 68 + col] = make_float2(cacc[mt][nt][0], cacc[mt][nt][1]);
                *(float2*)&sPf[(row + 8) * 68 + col] = make_float2(cacc[mt][nt][2], cacc[mt][nt][3]);
            }
    }
    __syncthreads();
    if (wk2 == 0) {
        __half* cb = g_ctx + (size_t)(b * SEQ + qt) * DIM + h * HD;
#pragma unroll
        for (int mt = 0; mt < 4; mt++)
#pragma unroll
            for (int nt = 0; nt < 4; nt++) {
                int row = wm + mt * 16 + g;
                int col = wn2 + nt * 8 + 2 * tg;
                float2 o0 = *(float2*)&sPf[row * 68 + col];
                float2 o1 = *(float2*)&sPf[(row + 8) * 68 + col];
                *(uint32_t*)(cb + (size_t)row * DIM + col) =
                    h2u(o0.x + cacc[mt][nt][0], o0.y + cacc[mt][nt][1]);
                *(uint32_t*)(cb + (size_t)(row + 8) * DIM + col) =
                    h2u(o1.x + cacc[mt][nt][2], o1.y + cacc[mt][nt][3]);
            }
    }
}

// =====================================================================
extern "C" void kernel_launch(void* const* d_in, const int* in_sizes, int n_in,
                              void* d_out, int out_size) {
    const float* x = (const float*)d_in[0];
    const float* wq = (const float*)d_in[1];
    const float* wk = (const float*)d_in[2];
    const float* wv = (const float*)d_in[3];
    const float* wo = (const float*)d_in[4];
    float* out = (float*)d_out;

    __half *q, *k, *v, *ctx, *xr, *wr;
    cudaGetSymbolAddress((void**)&q, g_q);
    cudaGetSymbolAddress((void**)&k, g_k);
    cudaGetSymbolAddress((void**)&v, g_v);
    cudaGetSymbolAddress((void**)&ctx, g_ctx);
    cudaGetSymbolAddress((void**)&xr, g_x);
    cudaGetSymbolAddress((void**)&wr, g_w);

    static int attr_done = 0;
    if (!attr_done) {
        cudaFuncSetAttribute(gemm_fp16, cudaFuncAttributeMaxDynamicSharedMemorySize, G_SMEM);
        cudaFuncSetAttribute(attn_z, cudaFuncAttributeMaxDynamicSharedMemorySize, Z_SMEM);
        cudaFuncSetAttribute(attn_ctx, cudaFuncAttributeMaxDynamicSharedMemorySize, C_SMEM);
        attr_done = 1;
    }

    round_x_h<<<2048, 256>>>(x);
    round_w_t<<<dim3(32, 32, 4), 256>>>(wq, wk, wv, wo);

    dim3 gg(DIM / 256, MTOT / 128);  // (4, 64)
    gemm_fp16<<<gg, 256, G_SMEM>>>(xr, wr + 0 * DIM * DIM, q, 1, QSCALE);
    gemm_fp16<<<gg, 256, G_SMEM>>>(xr, wr + 1 * DIM * DIM, k, 1, 1.0f);
    gemm_fp16<<<gg, 256, G_SMEM>>>(xr, wr + 2 * DIM * DIM, v, 1, 1.0f);

    transpose_v<<<dim3(SEQ / 32, DIM / 32, BATCH), 256>>>();

    attn_z<<<dim3(SEQ / 128, SEQ / 128, BATCH), 256, Z_SMEM>>>();

    attn_ctx<<<dim3(NH, SEQ / 128, BATCH), 256, C_SMEM>>>();

    gemm_fp16<<<gg, 256, G_SMEM>>>(ctx, wr + 3 * DIM * DIM, out, 0, 1.0f);
}

// round 12
// speedup vs baseline: 1.1059x; 1.0674x over previous
#include <cuda_runtime.h>
#include <cuda_fp16.h>
#include <stdint.h>

#define BATCH 4
#define SEQ   2048
#define DIM   1024
#define NH    16
#define HD    64
#define MTOT  (BATCH*SEQ)
// scale*log2(e): folded into q so 2^score = exp(0.125*qk)
#define QSCALE 0.1803368801111204f

// ---- scratch ----
__device__ __half g_q[MTOT * DIM];
__device__ __half g_k[MTOT * DIM];
__device__ __half g_v[MTOT * DIM];    // [b*S+s][n]  (temp)
__device__ __half g_vT[MTOT * DIM];   // [(b*NH+h)*HD+d][s]
__device__ __half g_ctx[MTOT * DIM];
__device__ __half g_x[MTOT * DIM];
__device__ __half g_w[4 * DIM * DIM]; // W^T, [n][k]
__device__ __half g_r[(size_t)BATCH * SEQ * SEQ];  // 1/Z, fp16

// ---- helpers ----
__device__ __forceinline__ uint32_t h2u(float a, float b) {
    __half2 h = __floats2half2_rn(a, b);
    return *(uint32_t*)&h;
}
__device__ __forceinline__ void mma16(float c[4], const uint32_t a[4], const uint32_t b[2]) {
    asm volatile(
        "mma.sync.aligned.m16n8k16.row.col.f32.f16.f16.f32 "
        "{%0,%1,%2,%3}, {%4,%5,%6,%7}, {%8,%9}, {%0,%1,%2,%3};\n"
        : "+f"(c[0]), "+f"(c[1]), "+f"(c[2]), "+f"(c[3])
        : "r"(a[0]), "r"(a[1]), "r"(a[2]), "r"(a[3]), "r"(b[0]), "r"(b[1]));
}
__device__ __forceinline__ void ldsm4(uint32_t r[4], const uint32_t* p) {
    uint32_t a = (uint32_t)__cvta_generic_to_shared(p);
    asm volatile("ldmatrix.sync.aligned.m8n8.x4.shared.b16 {%0,%1,%2,%3}, [%4];\n"
                 : "=r"(r[0]), "=r"(r[1]), "=r"(r[2]), "=r"(r[3]) : "r"(a));
}
__device__ __forceinline__ void cpa16(void* s, const void* g) {
    uint32_t sa = (uint32_t)__cvta_generic_to_shared(s);
    asm volatile("cp.async.ca.shared.global [%0], [%1], 16;\n" ::"r"(sa), "l"(g));
}
__device__ __forceinline__ void cp_commit() { asm volatile("cp.async.commit_group;\n"); }
template <int N>
__device__ __forceinline__ void cp_wait() { asm volatile("cp.async.wait_group %0;\n" ::"n"(N)); }

// =====================================================================
// x -> fp16
// =====================================================================
__global__ void round_x_h(const float* __restrict__ x) {
    const int n4 = MTOT * DIM / 4;
    uint2* out = (uint2*)g_x;
    int i = blockIdx.x * blockDim.x + threadIdx.x;
    int stride = gridDim.x * blockDim.x;
    for (; i < n4; i += stride) {
        float4 v = ((const float4*)x)[i];
        uint2 o;
        o.x = h2u(v.x, v.y);
        o.y = h2u(v.z, v.w);
        out[i] = o;
    }
}

// =====================================================================
// weights -> fp16, transposed to [n][k]
// =====================================================================
__global__ void round_w_t(const float* __restrict__ w0, const float* __restrict__ w1,
                          const float* __restrict__ w2, const float* __restrict__ w3) {
    __shared__ float t[32][33];
    const float* src = (blockIdx.z == 0) ? w0 : (blockIdx.z == 1) ? w1 : (blockIdx.z == 2) ? w2 : w3;
    __half* dst = g_w + (size_t)blockIdx.z * DIM * DIM;
    const int k0 = blockIdx.y * 32, n0 = blockIdx.x * 32;
    const int r = threadIdx.x >> 5, cc = threadIdx.x & 31;
#pragma unroll
    for (int i = 0; i < 4; i++) t[r + i * 8][cc] = src[(size_t)(k0 + r + i * 8) * DIM + n0 + cc];
    __syncthreads();
#pragma unroll
    for (int i = 0; i < 4; i++)
        dst[(size_t)(n0 + r + i * 8) * DIM + k0 + cc] = __float2half_rn(t[cc][r + i * 8]);
}

// =====================================================================
// v [s][n] -> vT [n][s], per batch
// =====================================================================
__global__ void transpose_v() {
    __shared__ __half t[32][33];
    const int b = blockIdx.z, s0 = blockIdx.x * 32, n0 = blockIdx.y * 32;
    const int r = threadIdx.x >> 5, cc = threadIdx.x & 31;
#pragma unroll
    for (int i = 0; i < 4; i++)
        t[r + i * 8][cc] = g_v[(size_t)(b * SEQ + s0 + r + i * 8) * DIM + n0 + cc];
    __syncthreads();
#pragma unroll
    for (int i = 0; i < 4; i++)
        g_vT[((size_t)b * DIM + n0 + r + i * 8) * SEQ + s0 + cc] = t[cc][r + i * 8];
}

// =====================================================================
// GEMM: C[M,1024] = (A @ W) * out_scale  (A fp16 [m][k], W^T fp16 [n][k]).
// Block 128x256, k-stage 64, 8 warps (2m x 4n), warp 64x64, GS=3, LDSM.
// =====================================================================
#define GS 3
#define GA_W (128 * 36)
#define GB_W (256 * 36)
#define G_SMEM (GS * (GA_W + GB_W) * 4)

__global__ __launch_bounds__(256) void gemm_fp16(const __half* __restrict__ A,
                                                 const __half* __restrict__ WT,
                                                 void* __restrict__ Cout, int half_out,
                                                 float out_scale) {
    extern __shared__ uint32_t smu[];
    uint32_t* sA = smu;
    uint32_t* sB = smu + GS * GA_W;
    const int tid = threadIdx.x;
    const int m0 = blockIdx.y * 128, n0 = blockIdx.x * 256;
    const int w = tid >> 5, lane = tid & 31, g = lane >> 2, tg = lane & 3;
    const int wm = (w >> 2) * 64, wn = (w & 3) * 64;
    const int lrA = (lane & 7) + ((lane >> 3) & 1) * 8, lcA = (lane >> 4) * 4;
    const int lrB = (lane & 7) + (lane >> 4) * 8, lcB = ((lane >> 3) & 1) * 4;

    float acc[4][8][4]{};

    auto load_tile = [&](int st, int kt) {
        uint32_t* a = sA + st * GA_W;
        uint32_t* bb = sB + st * GB_W;
#pragma unroll
        for (int i = 0; i < 4; i++) {
            int c = tid + 256 * i;
            int r = c >> 3, cw = (c & 7) * 4;
            cpa16(a + r * 36 + cw, A + (size_t)(m0 + r) * DIM + kt + cw * 2);
        }
#pragma unroll
        for (int i = 0; i < 8; i++) {
            int c = tid + 256 * i;
            int r = c >> 3, cw = (c & 7) * 4;
            cpa16(bb + r * 36 + cw, WT + (size_t)(n0 + r) * DIM + kt + cw * 2);
        }
    };

    const int NK = DIM / 64;  // 16
#pragma unroll
    for (int s = 0; s < GS - 1; s++) {
        load_tile(s, s * 64);
        cp_commit();
    }
    for (int t = 0; t < NK; t++) {
        cp_wait<GS - 2>();
        __syncthreads();
        int ld = t + GS - 1;
        if (ld < NK) load_tile(ld % GS, ld * 64);
        cp_commit();
        const uint32_t* a = sA + (t % GS) * GA_W;
        const uint32_t* b = sB + (t % GS) * GB_W;
#pragma unroll
        for (int kw = 0; kw < 32; kw += 8) {
            uint32_t af[4][4], bf[8][2];
#pragma unroll
            for (int mt = 0; mt < 4; mt++)
                ldsm4(af[mt], a + (wm + mt * 16 + lrA) * 36 + kw + lcA);
#pragma unroll
            for (int np = 0; np < 4; np++) {
                uint32_t tmp[4];
                ldsm4(tmp, b + (wn + np * 16 + lrB) * 36 + kw + lcB);
                bf[2 * np][0] = tmp[0];
                bf[2 * np][1] = tmp[1];
                bf[2 * np + 1][0] = tmp[2];
                bf[2 * np + 1][1] = tmp[3];
            }
#pragma unroll
            for (int mt = 0; mt < 4; mt++)
#pragma unroll
                for (int nt = 0; nt < 8; nt++) mma16(acc[mt][nt], af[mt], bf[nt]);
        }
    }
#pragma unroll
    for (int mt = 0; mt < 4; mt++)
#pragma unroll
        for (int nt = 0; nt < 8; nt++) {
            int row = m0 + wm + mt * 16 + g;
            int col = n0 + wn + nt * 8 + 2 * tg;
            if (half_out) {
                __half* C = (__half*)Cout;
                *(uint32_t*)(C + (size_t)row * DIM + col) =
                    h2u(acc[mt][nt][0] * out_scale, acc[mt][nt][1] * out_scale);
                *(uint32_t*)(C + (size_t)(row + 8) * DIM + col) =
                    h2u(acc[mt][nt][2] * out_scale, acc[mt][nt][3] * out_scale);
            } else {
                float* C = (float*)Cout;
                *(float2*)(C + (size_t)row * DIM + col) = make_float2(acc[mt][nt][0], acc[mt][nt][1]);
                *(float2*)(C + (size_t)(row + 8) * DIM + col) = make_float2(acc[mt][nt][2], acc[mt][nt][3]);
            }
        }
}

// =====================================================================
// Pass A: R = 1 / sum_h 2^(q.k)   (q pre-scaled by scale*log2e)
// fp16 MMA, LDSM, half2 ex2 epilogue.
// =====================================================================
#define ZT_W (128 * 36)
#define Z_SMEM (4 * ZT_W * 4)

__global__ __launch_bounds__(256) void attn_z() {
    extern __shared__ uint32_t smu[];
    uint32_t* sQ = smu;
    uint32_t* sK = smu + 2 * ZT_W;
    const int tid = threadIdx.x;
    const int b = blockIdx.z, qt = blockIdx.y * 128, kt = blockIdx.x * 128;
    const int w = tid >> 5, lane = tid & 31, g = lane >> 2, tg = lane & 3;
    const int wm = (w >> 2) * 64, wn = (w & 3) * 32;
    const int lrA = (lane & 7) + ((lane >> 3) & 1) * 8, lcA = (lane >> 4) * 4;
    const int lrB = (lane & 7) + (lane >> 4) * 8, lcB = ((lane >> 3) & 1) * 4;

    const __half* qb = g_q + (size_t)(b * SEQ + qt) * DIM;
    const __half* kb = g_k + (size_t)(b * SEQ + kt) * DIM;

    auto load_head = [&](int st, int h) {
        uint32_t* q = sQ + st * ZT_W;
        uint32_t* k = sK + st * ZT_W;
#pragma unroll
        for (int i = 0; i < 4; i++) {
            int c = tid + 256 * i;
            int r = c >> 3, cw = (c & 7) * 4;
            cpa16(q + r * 36 + cw, qb + (size_t)r * DIM + h * HD + cw * 2);
            cpa16(k + r * 36 + cw, kb + (size_t)r * DIM + h * HD + cw * 2);
        }
    };

    float zacc[4][4][4]{};
    load_head(0, 0);
    cp_commit();

    for (int h = 0; h < NH; h++) {
        cp_wait<0>();
        __syncthreads();
        if (h + 1 < NH) load_head((h + 1) & 1, h + 1);
        cp_commit();
        const uint32_t* q = sQ + (h & 1) * ZT_W;
        const uint32_t* k = sK + (h & 1) * ZT_W;

        float sacc[4][4][4]{};
#pragma unroll
        for (int kw = 0; kw < 32; kw += 8) {
            uint32_t af[4][4], bf[4][2];
#pragma unroll
            for (int mt = 0; mt < 4; mt++)
                ldsm4(af[mt], q + (wm + mt * 16 + lrA) * 36 + kw + lcA);
#pragma unroll
            for (int np = 0; np < 2; np++) {
                uint32_t tmp[4];
                ldsm4(tmp, k + (wn + np * 16 + lrB) * 36 + kw + lcB);
                bf[2 * np][0] = tmp[0];
                bf[2 * np][1] = tmp[1];
                bf[2 * np + 1][0] = tmp[2];
                bf[2 * np + 1][1] = tmp[3];
            }
#pragma unroll
            for (int mt = 0; mt < 4; mt++)
#pragma unroll
                for (int nt = 0; nt < 4; nt++) mma16(sacc[mt][nt], af[mt], bf[nt]);
        }
        // zacc += 2^sacc  via half2 ex2 (one MUFU per 2 values)
#pragma unroll
        for (int i = 0; i < 4; i++)
#pragma unroll
            for (int j = 0; j < 4; j++) {
                __half2 s0 = __floats2half2_rn(sacc[i][j][0], sacc[i][j][1]);
                __half2 s1 = __floats2half2_rn(sacc[i][j][2], sacc[i][j][3]);
                float2 e0 = __half22float2(h2exp2(s0));
                float2 e1 = __half22float2(h2exp2(s1));
                zacc[i][j][0] += e0.x;
                zacc[i][j][1] += e0.y;
                zacc[i][j][2] += e1.x;
                zacc[i][j][3] += e1.y;
            }
    }
#pragma unroll
    for (int mt = 0; mt < 4; mt++)
#pragma unroll
        for (int nt = 0; nt < 4; nt++) {
            int row = qt + wm + mt * 16 + g;
            int col = kt + wn + nt * 8 + 2 * tg;
            __half* rp = g_r + ((size_t)b * SEQ + row) * SEQ + col;
            *(uint32_t*)rp = h2u(1.f / zacc[mt][nt][0], 1.f / zacc[mt][nt][1]);
            *(uint32_t*)(rp + (size_t)8 * SEQ) = h2u(1.f / zacc[mt][nt][2], 1.f / zacc[mt][nt][3]);
        }
}

// =====================================================================
// Pass B: ctx = sum_k 2^(q.k) * R * V  per (b,h,qtile)  (fp16, LDSM)
// Fragment reuse: GEMM1 C-fragments become GEMM2 A-fragments in regs
// (no P smem round-trip). GEMM2 k-split == GEMM1 n-split (4 x 32).
// K/V/R double-buffered; final 4-way k-slice reduction via sR buffer.
// =====================================================================
#define CQ_W (128 * 36)
#define CVT_W (64 * 68)
#define CR_W (128 * 68)   // fp16 R tile: 128 x 136 halves per slot
// sQ | sK[2] | sV[2] | sR[2]
#define C_SMEM ((3 * CQ_W + 2 * CVT_W + 2 * CR_W) * 4)

__global__ __launch_bounds__(256) void attn_ctx() {
    extern __shared__ uint32_t smu[];
    uint32_t* sQ = smu;
    uint32_t* sK = smu + CQ_W;                  // 2 slots
    uint32_t* sV = smu + 3 * CQ_W;              // 2 slots
    uint32_t* sR = smu + 3 * CQ_W + 2 * CVT_W;  // 2 slots (fp16 tiles)

    const int tid = threadIdx.x;
    const int b = blockIdx.z, h = blockIdx.x, qt = blockIdx.y * 128;
    const int w = tid >> 5, lane = tid & 31, g = lane >> 2, tg = lane & 3;
    const int wm = (w >> 2) * 64, wn = (w & 3) * 32;  // wn = GEMM1 n-slice = GEMM2 k-slice
    const int lrA = (lane & 7) + ((lane >> 3) & 1) * 8, lcA = (lane >> 4) * 4;
    const int lrB = (lane & 7) + (lane >> 4) * 8, lcB = ((lane >> 3) & 1) * 4;

    const int NT = SEQ / 128;

    auto load_kvr = [&](int t) {
        int slot = t & 1;
        const __half* kb = g_k + (size_t)(b * SEQ + t * 128) * DIM + h * HD;
        uint32_t* kd = sK + slot * CQ_W;
#pragma unroll
        for (int i = 0; i < 4; i++) {
            int c = tid + 256 * i;
            int r = c >> 3, cw = (c & 7) * 4;
            cpa16(kd + r * 36 + cw, kb + (size_t)r * DIM + cw * 2);
        }
        const __half* vtb = g_vT + ((size_t)(b * NH + h) * HD) * SEQ + t * 128;
        uint32_t* vd = sV + slot * CVT_W;
#pragma unroll
        for (int i = 0; i < 4; i++) {
            int c = tid + 256 * i;
            int r = c >> 4, cw = (c & 15) * 4;
            cpa16(vd + r * 68 + cw, vtb + (size_t)r * SEQ + cw * 2);
        }
        const __half* rb = g_r + ((size_t)b * SEQ + qt) * SEQ + t * 128;
        __half* rd = (__half*)(sR + slot * CR_W);
#pragma unroll
        for (int i = 0; i < 8; i++) {
            int c = tid + 256 * i;
            int r = c >> 4, ch = (c & 15) * 8;
            cpa16(rd + r * 136 + ch, rb + (size_t)r * SEQ + ch);
        }
    };

    // prologue: Q + tiles 0 and 1
    {
        const __half* qb = g_q + (size_t)(b * SEQ + qt) * DIM + h * HD;
#pragma unroll
        for (int i = 0; i < 4; i++) {
            int c = tid + 256 * i;
            int r = c >> 3, cw = (c & 7) * 4;
            cpa16(sQ + r * 36 + cw, qb + (size_t)r * DIM + cw * 2);
        }
        load_kvr(0);
        cp_commit();  // group 0
        load_kvr(1);
        cp_commit();  // group 1
    }

    float cacc[4][8][4]{};  // ctx partial: 64m x 64n over this warp's 32-k slice

    for (int t = 0; t < NT; t++) {
        cp_wait<1>();  // group t complete
        __syncthreads();

        // GEMM1: S = Q @ K^T (128x128x64), log2-domain scores
        const uint32_t* kc = sK + (t & 1) * CQ_W;
        float sacc[4][4][4]{};
#pragma unroll
        for (int kw = 0; kw < 32; kw += 8) {
            uint32_t af[4][4], bf[4][2];
#pragma unroll
            for (int mt = 0; mt < 4; mt++)
                ldsm4(af[mt], sQ + (wm + mt * 16 + lrA) * 36 + kw + lcA);
#pragma unroll
            for (int np = 0; np < 2; np++) {
                uint32_t tmp[4];
                ldsm4(tmp, kc + (wn + np * 16 + lrB) * 36 + kw + lcB);
                bf[2 * np][0] = tmp[0];
                bf[2 * np][1] = tmp[1];
                bf[2 * np + 1][0] = tmp[2];
                bf[2 * np + 1][1] = tmp[3];
            }
#pragma unroll
            for (int mt = 0; mt < 4; mt++)
#pragma unroll
                for (int nt = 0; nt < 4; nt++) mma16(sacc[mt][nt], af[mt], bf[nt]);
        }

        // Epilogue in registers: pa = 2^sacc * R  (A-fragments for GEMM2)
        const __half* rslot = (const __half*)(sR + (t & 1) * CR_W);
        uint32_t pa[4][2][4];
#pragma unroll
        for (int mt = 0; mt < 4; mt++)
#pragma unroll
            for (int kb = 0; kb < 2; kb++) {
                int row = wm + mt * 16 + g;
                int col = wn + (2 * kb) * 8 + 2 * tg;  // nt_lo column
                __half2 r0 = *(__half2*)(rslot + row * 136 + col);
                __half2 r1 = *(__half2*)(rslot + (row + 8) * 136 + col);
                __half2 r2 = *(__half2*)(rslot + row * 136 + col + 8);
                __half2 r3 = *(__half2*)(rslot + (row + 8) * 136 + col + 8);
                int lo = 2 * kb, hi = 2 * kb + 1;
                __half2 p0 = __hmul2(h2exp2(__floats2half2_rn(sacc[mt][lo][0], sacc[mt][lo][1])), r0);
                __half2 p1 = __hmul2(h2exp2(__floats2half2_rn(sacc[mt][lo][2], sacc[mt][lo][3])), r1);
                __half2 p2 = __hmul2(h2exp2(__floats2half2_rn(sacc[mt][hi][0], sacc[mt][hi][1])), r2);
                __half2 p3 = __hmul2(h2exp2(__floats2half2_rn(sacc[mt][hi][2], sacc[mt][hi][3])), r3);
                pa[mt][kb][0] = *(uint32_t*)&p0;
                pa[mt][kb][1] = *(uint32_t*)&p1;
                pa[mt][kb][2] = *(uint32_t*)&p2;
                pa[mt][kb][3] = *(uint32_t*)&p3;
            }

        // GEMM2: cacc += P_slice @ V_slice (64m x 64n x 32k per warp)
        const uint32_t* vslot = sV + (t & 1) * CVT_W;
        const int kwBase = wn >> 1;  // word offset of this warp's k-slice in sVT rows
#pragma unroll
        for (int kb = 0; kb < 2; kb++) {
            uint32_t bf[8][2];
#pragma unroll
            for (int np = 0; np < 4; np++) {
                uint32_t tmp[4];
                ldsm4(tmp, vslot + (np * 16 + lrB) * 68 + kwBase + kb * 8 + lcB);
                bf[2 * np][0] = tmp[0];
                bf[2 * np][1] = tmp[1];
                bf[2 * np + 1][0] = tmp[2];
                bf[2 * np + 1][1] = tmp[3];
            }
#pragma unroll
            for (int mt = 0; mt < 4; mt++)
#pragma unroll
                for (int nt = 0; nt < 8; nt++) mma16(cacc[mt][nt], pa[mt][kb], bf[nt]);
        }
        __syncthreads();  // slot (t&1) consumed by all warps

        if (t + 2 < NT) load_kvr(t + 2);
        cp_commit();
    }

    // 4-way k-slice reduction via sR (free now): red[2][64][68] fp32
    float* red = (float*)sR;
    const int ks = w & 3, mg = w >> 2;
    float* rbase = red + mg * 64 * 68;
#pragma unroll
    for (int s = 1; s < 4; s++) {
        if (ks == s) {
#pragma unroll
            for (int mt = 0; mt < 4; mt++)
#pragma unroll
                for (int nt = 0; nt < 8; nt++) {
                    int row = mt * 16 + g;
                    int col = nt * 8 + 2 * tg;
                    if (s == 1) {
                        *(float2*)&rbase[row * 68 + col] = make_float2(cacc[mt][nt][0], cacc[mt][nt][1]);
                        *(float2*)&rbase[(row + 8) * 68 + col] = make_float2(cacc[mt][nt][2], cacc[mt][nt][3]);
                    } else {
                        float2 a0 = *(float2*)&rbase[row * 68 + col];
                        float2 a1 = *(float2*)&rbase[(row + 8) * 68 + col];
                        a0.x += cacc[mt][nt][0];
                        a0.y += cacc[mt][nt][1];
                        a1.x += cacc[mt][nt][2];
                        a1.y += cacc[mt][nt][3];
                        *(float2*)&rbase[row * 68 + col] = a0;
                        *(float2*)&rbase[(row + 8) * 68 + col] = a1;
                    }
                }
        }
        __syncthreads();
    }
    if (ks == 0) {
        __half* cb = g_ctx + (size_t)(b * SEQ + qt) * DIM + h * HD;
#pragma unroll
        for (int mt = 0; mt < 4; mt++)
#pragma unroll
            for (int nt = 0; nt < 8; nt++) {
                int row = mt * 16 + g;
                int col = nt * 8 + 2 * tg;
                float2 o0 = *(float2*)&rbase[row * 68 + col];
                float2 o1 = *(float2*)&rbase[(row + 8) * 68 + col];
                *(uint32_t*)(cb + (size_t)(wm + row) * DIM + col) =
                    h2u(o0.x + cacc[mt][nt][0], o0.y + cacc[mt][nt][1]);
                *(uint32_t*)(cb + (size_t)(wm + row + 8) * DIM + col) =
                    h2u(o1.x + cacc[mt][nt][2], o1.y + cacc[mt][nt][3]);
            }
    }
}

// =====================================================================
extern "C" void kernel_launch(void* const* d_in, const int* in_sizes, int n_in,
                              void* d_out, int out_size) {
    const float* x = (const float*)d_in[0];
    const float* wq = (const float*)d_in[1];
    const float* wk = (const float*)d_in[2];
    const float* wv = (const float*)d_in[3];
    const float* wo = (const float*)d_in[4];
    float* out = (float*)d_out;

    __half *q, *k, *v, *ctx, *xr, *wr;
    cudaGetSymbolAddress((void**)&q, g_q);
    cudaGetSymbolAddress((void**)&k, g_k);
    cudaGetSymbolAddress((void**)&v, g_v);
    cudaGetSymbolAddress((void**)&ctx, g_ctx);
    cudaGetSymbolAddress((void**)&xr, g_x);
    cudaGetSymbolAddress((void**)&wr, g_w);

    static int attr_done = 0;
    if (!attr_done) {
        cudaFuncSetAttribute(gemm_fp16, cudaFuncAttributeMaxDynamicSharedMemorySize, G_SMEM);
        cudaFuncSetAttribute(attn_z, cudaFuncAttributeMaxDynamicSharedMemorySize, Z_SMEM);
        cudaFuncSetAttribute(attn_ctx, cudaFuncAttributeMaxDynamicSharedMemorySize, C_SMEM);
        attr_done = 1;
    }

    round_x_h<<<2048, 256>>>(x);
    round_w_t<<<dim3(32, 32, 4), 256>>>(wq, wk, wv, wo);

    dim3 gg(DIM / 256, MTOT / 128);  // (4, 64)
    gemm_fp16<<<gg, 256, G_SMEM>>>(xr, wr + 0 * DIM * DIM, q, 1, QSCALE);
    gemm_fp16<<<gg, 256, G_SMEM>>>(xr, wr + 1 * DIM * DIM, k, 1, 1.0f);
    gemm_fp16<<<gg, 256, G_SMEM>>>(xr, wr + 2 * DIM * DIM, v, 1, 1.0f);

    transpose_v<<<dim3(SEQ / 32, DIM / 32, BATCH), 256>>>();

    attn_z<<<dim3(SEQ / 128, SEQ / 128, BATCH), 256, Z_SMEM>>>();

    attn_ctx<<<dim3(NH, SEQ / 128, BATCH), 256, C_SMEM>>>();

    gemm_fp16<<<gg, 256, G_SMEM>>>(ctx, wr + 3 * DIM * DIM, out, 0, 1.0f);
}

// round 14
// speedup vs baseline: 1.1924x; 1.0782x over previous
#include <cuda_runtime.h>
#include <cuda_fp16.h>
#include <stdint.h>

#define BATCH 4
#define SEQ   2048
#define DIM   1024
#define NH    16
#define HD    64
#define MTOT  (BATCH*SEQ)
// scale*log2(e): folded into q so 2^score = exp(0.125*qk)
#define QSCALE 0.1803368801111204f

// ---- scratch ----
__device__ __half g_q[MTOT * DIM];
__device__ __half g_k[MTOT * DIM];
__device__ __half g_v[MTOT * DIM];    // [b*S+s][n]  (temp)
__device__ __half g_vT[MTOT * DIM];   // [(b*NH+h)*HD+d][s]
__device__ __half g_ctx[MTOT * DIM];
__device__ __half g_x[MTOT * DIM];
__device__ __half g_w[4 * DIM * DIM]; // W^T, [n][k]
__device__ __half g_r[(size_t)BATCH * SEQ * SEQ];  // 1/Z, fp16

// ---- helpers ----
__device__ __forceinline__ uint32_t h2u(float a, float b) {
    __half2 h = __floats2half2_rn(a, b);
    return *(uint32_t*)&h;
}
__device__ __forceinline__ void mma16(float c[4], const uint32_t a[4], const uint32_t b[2]) {
    asm volatile(
        "mma.sync.aligned.m16n8k16.row.col.f32.f16.f16.f32 "
        "{%0,%1,%2,%3}, {%4,%5,%6,%7}, {%8,%9}, {%0,%1,%2,%3};\n"
        : "+f"(c[0]), "+f"(c[1]), "+f"(c[2]), "+f"(c[3])
        : "r"(a[0]), "r"(a[1]), "r"(a[2]), "r"(a[3]), "r"(b[0]), "r"(b[1]));
}
// fp16 accumulator variant: C fragment = 2 x half2 (row g, row g+8)
__device__ __forceinline__ void mma16h(uint32_t c[2], const uint32_t a[4], const uint32_t b[2]) {
    asm volatile(
        "mma.sync.aligned.m16n8k16.row.col.f16.f16.f16.f16 "
        "{%0,%1}, {%2,%3,%4,%5}, {%6,%7}, {%0,%1};\n"
        : "+r"(c[0]), "+r"(c[1])
        : "r"(a[0]), "r"(a[1]), "r"(a[2]), "r"(a[3]), "r"(b[0]), "r"(b[1]));
}
__device__ __forceinline__ void ldsm4(uint32_t r[4], const uint32_t* p) {
    uint32_t a = (uint32_t)__cvta_generic_to_shared(p);
    asm volatile("ldmatrix.sync.aligned.m8n8.x4.shared.b16 {%0,%1,%2,%3}, [%4];\n"
                 : "=r"(r[0]), "=r"(r[1]), "=r"(r[2]), "=r"(r[3]) : "r"(a));
}
__device__ __forceinline__ void cpa16(void* s, const void* g) {
    uint32_t sa = (uint32_t)__cvta_generic_to_shared(s);
    asm volatile("cp.async.ca.shared.global [%0], [%1], 16;\n" ::"r"(sa), "l"(g));
}
__device__ __forceinline__ void cp_commit() { asm volatile("cp.async.commit_group;\n"); }
template <int N>
__device__ __forceinline__ void cp_wait() { asm volatile("cp.async.wait_group %0;\n" ::"n"(N)); }

// =====================================================================
// x -> fp16
// =====================================================================
__global__ void round_x_h(const float* __restrict__ x) {
    const int n4 = MTOT * DIM / 4;
    uint2* out = (uint2*)g_x;
    int i = blockIdx.x * blockDim.x + threadIdx.x;
    int stride = gridDim.x * blockDim.x;
    for (; i < n4; i += stride) {
        float4 v = ((const float4*)x)[i];
        uint2 o;
        o.x = h2u(v.x, v.y);
        o.y = h2u(v.z, v.w);
        out[i] = o;
    }
}

// =====================================================================
// weights -> fp16, transposed to [n][k]
// =====================================================================
__global__ void round_w_t(const float* __restrict__ w0, const float* __restrict__ w1,
                          const float* __restrict__ w2, const float* __restrict__ w3) {
    __shared__ float t[32][33];
    const float* src = (blockIdx.z == 0) ? w0 : (blockIdx.z == 1) ? w1 : (blockIdx.z == 2) ? w2 : w3;
    __half* dst = g_w + (size_t)blockIdx.z * DIM * DIM;
    const int k0 = blockIdx.y * 32, n0 = blockIdx.x * 32;
    const int r = threadIdx.x >> 5, cc = threadIdx.x & 31;
#pragma unroll
    for (int i = 0; i < 4; i++) t[r + i * 8][cc] = src[(size_t)(k0 + r + i * 8) * DIM + n0 + cc];
    __syncthreads();
#pragma unroll
    for (int i = 0; i < 4; i++)
        dst[(size_t)(n0 + r + i * 8) * DIM + k0 + cc] = __float2half_rn(t[cc][r + i * 8]);
}

// =====================================================================
// v [s][n] -> vT [n][s], per batch
// =====================================================================
__global__ void transpose_v() {
    __shared__ __half t[32][33];
    const int b = blockIdx.z, s0 = blockIdx.x * 32, n0 = blockIdx.y * 32;
    const int r = threadIdx.x >> 5, cc = threadIdx.x & 31;
#pragma unroll
    for (int i = 0; i < 4; i++)
        t[r + i * 8][cc] = g_v[(size_t)(b * SEQ + s0 + r + i * 8) * DIM + n0 + cc];
    __syncthreads();
#pragma unroll
    for (int i = 0; i < 4; i++)
        g_vT[((size_t)b * DIM + n0 + r + i * 8) * SEQ + s0 + cc] = t[cc][r + i * 8];
}

// =====================================================================
// GEMM body (fp32 acc): C[M,1024] = (A @ W) * out_scale
// Block 128x256, k-stage 64, 8 warps (2m x 4n), warp 64x64, GS=3, LDSM.
// =====================================================================
#define GS 3
#define GA_W (128 * 36)
#define GB_W (256 * 36)
#define G_SMEM (GS * (GA_W + GB_W) * 4)

__device__ __forceinline__ void gemm_body(const __half* __restrict__ A,
                                          const __half* __restrict__ WT,
                                          void* __restrict__ Cout, int half_out,
                                          float out_scale, int bx, int by) {
    extern __shared__ uint32_t smu[];
    uint32_t* sA = smu;
    uint32_t* sB = smu + GS * GA_W;
    const int tid = threadIdx.x;
    const int m0 = by * 128, n0 = bx * 256;
    const int w = tid >> 5, lane = tid & 31, g = lane >> 2, tg = lane & 3;
    const int wm = (w >> 2) * 64, wn = (w & 3) * 64;
    const int lrA = (lane & 7) + ((lane >> 3) & 1) * 8, lcA = (lane >> 4) * 4;
    const int lrB = (lane & 7) + (lane >> 4) * 8, lcB = ((lane >> 3) & 1) * 4;

    float acc[4][8][4]{};

    auto load_tile = [&](int st, int kt) {
        uint32_t* a = sA + st * GA_W;
        uint32_t* bb = sB + st * GB_W;
#pragma unroll
        for (int i = 0; i < 4; i++) {
            int c = tid + 256 * i;
            int r = c >> 3, cw = (c & 7) * 4;
            cpa16(a + r * 36 + cw, A + (size_t)(m0 + r) * DIM + kt + cw * 2);
        }
#pragma unroll
        for (int i = 0; i < 8; i++) {
            int c = tid + 256 * i;
            int r = c >> 3, cw = (c & 7) * 4;
            cpa16(bb + r * 36 + cw, WT + (size_t)(n0 + r) * DIM + kt + cw * 2);
        }
    };

    const int NK = DIM / 64;  // 16
#pragma unroll
    for (int s = 0; s < GS - 1; s++) {
        load_tile(s, s * 64);
        cp_commit();
    }
    for (int t = 0; t < NK; t++) {
        cp_wait<GS - 2>();
        __syncthreads();
        int ld = t + GS - 1;
        if (ld < NK) load_tile(ld % GS, ld * 64);
        cp_commit();
        const uint32_t* a = sA + (t % GS) * GA_W;
        const uint32_t* b = sB + (t % GS) * GB_W;
#pragma unroll
        for (int kw = 0; kw < 32; kw += 8) {
            uint32_t af[4][4], bf[8][2];
#pragma unroll
            for (int mt = 0; mt < 4; mt++)
                ldsm4(af[mt], a + (wm + mt * 16 + lrA) * 36 + kw + lcA);
#pragma unroll
            for (int np = 0; np < 4; np++) {
                uint32_t tmp[4];
                ldsm4(tmp, b + (wn + np * 16 + lrB) * 36 + kw + lcB);
                bf[2 * np][0] = tmp[0];
                bf[2 * np][1] = tmp[1];
                bf[2 * np + 1][0] = tmp[2];
                bf[2 * np + 1][1] = tmp[3];
            }
#pragma unroll
            for (int mt = 0; mt < 4; mt++)
#pragma unroll
                for (int nt = 0; nt < 8; nt++) mma16(acc[mt][nt], af[mt], bf[nt]);
        }
    }
#pragma unroll
    for (int mt = 0; mt < 4; mt++)
#pragma unroll
        for (int nt = 0; nt < 8; nt++) {
            int row = m0 + wm + mt * 16 + g;
            int col = n0 + wn + nt * 8 + 2 * tg;
            if (half_out) {
                __half* C = (__half*)Cout;
                *(uint32_t*)(C + (size_t)row * DIM + col) =
                    h2u(acc[mt][nt][0] * out_scale, acc[mt][nt][1] * out_scale);
                *(uint32_t*)(C + (size_t)(row + 8) * DIM + col) =
                    h2u(acc[mt][nt][2] * out_scale, acc[mt][nt][3] * out_scale);
            } else {
                float* C = (float*)Cout;
                *(float2*)(C + (size_t)row * DIM + col) = make_float2(acc[mt][nt][0], acc[mt][nt][1]);
                *(float2*)(C + (size_t)(row + 8) * DIM + col) = make_float2(acc[mt][nt][2], acc[mt][nt][3]);
            }
        }
}

__global__ __launch_bounds__(256) void gemm_fp16(const __half* __restrict__ A,
                                                 const __half* __restrict__ WT,
                                                 void* __restrict__ Cout, int half_out,
                                                 float out_scale) {
    gemm_body(A, WT, Cout, half_out, out_scale, blockIdx.x, blockIdx.y);
}

// fused q/k/v projections: grid.z selects weight / destination / scale
__global__ __launch_bounds__(256) void gemm_qkv(const __half* __restrict__ A) {
    const int z = blockIdx.z;
    const __half* WT = g_w + (size_t)z * DIM * DIM;
    __half* dst = (z == 0) ? g_q : (z == 1) ? g_k : g_v;
    float sc = (z == 0) ? QSCALE : 1.0f;
    gemm_body(A, WT, dst, 1, sc, blockIdx.x, blockIdx.y);
}

// =====================================================================
// Pass A: R = 1 / sum_h 2^(q.k)   (q pre-scaled by scale*log2e)
// fp16 MMA with fp16 accumulator (C frags feed h2exp2 directly).
// =====================================================================
#define ZT_W (128 * 36)
#define Z_SMEM (4 * ZT_W * 4)

__global__ __launch_bounds__(256) void attn_z() {
    extern __shared__ uint32_t smu[];
    uint32_t* sQ = smu;
    uint32_t* sK = smu + 2 * ZT_W;
    const int tid = threadIdx.x;
    const int b = blockIdx.z, qt = blockIdx.y * 128, kt = blockIdx.x * 128;
    const int w = tid >> 5, lane = tid & 31, g = lane >> 2, tg = lane & 3;
    const int wm = (w >> 2) * 64, wn = (w & 3) * 32;
    const int lrA = (lane & 7) + ((lane >> 3) & 1) * 8, lcA = (lane >> 4) * 4;
    const int lrB = (lane & 7) + (lane >> 4) * 8, lcB = ((lane >> 3) & 1) * 4;

    const __half* qb = g_q + (size_t)(b * SEQ + qt) * DIM;
    const __half* kb = g_k + (size_t)(b * SEQ + kt) * DIM;

    auto load_head = [&](int st, int h) {
        uint32_t* q = sQ + st * ZT_W;
        uint32_t* k = sK + st * ZT_W;
#pragma unroll
        for (int i = 0; i < 4; i++) {
            int c = tid + 256 * i;
            int r = c >> 3, cw = (c & 7) * 4;
            cpa16(q + r * 36 + cw, qb + (size_t)r * DIM + h * HD + cw * 2);
            cpa16(k + r * 36 + cw, kb + (size_t)r * DIM + h * HD + cw * 2);
        }
    };

    float zacc[4][4][4]{};
    load_head(0, 0);
    cp_commit();

    for (int h = 0; h < NH; h++) {
        cp_wait<0>();
        __syncthreads();
        if (h + 1 < NH) load_head((h + 1) & 1, h + 1);
        cp_commit();
        const uint32_t* q = sQ + (h & 1) * ZT_W;
        const uint32_t* k = sK + (h & 1) * ZT_W;

        uint32_t sacc[4][4][2]{};  // fp16 accumulators (half2 row g / row g+8)
#pragma unroll
        for (int kw = 0; kw < 32; kw += 8) {
            uint32_t af[4][4], bf[4][2];
#pragma unroll
            for (int mt = 0; mt < 4; mt++)
                ldsm4(af[mt], q + (wm + mt * 16 + lrA) * 36 + kw + lcA);
#pragma unroll
            for (int np = 0; np < 2; np++) {
                uint32_t tmp[4];
                ldsm4(tmp, k + (wn + np * 16 + lrB) * 36 + kw + lcB);
                bf[2 * np][0] = tmp[0];
                bf[2 * np][1] = tmp[1];
                bf[2 * np + 1][0] = tmp[2];
                bf[2 * np + 1][1] = tmp[3];
            }
#pragma unroll
            for (int mt = 0; mt < 4; mt++)
#pragma unroll
                for (int nt = 0; nt < 4; nt++) mma16h(sacc[mt][nt], af[mt], bf[nt]);
        }
        // zacc += 2^sacc : C frags are already half2 -> h2exp2 directly
#pragma unroll
        for (int i = 0; i < 4; i++)
#pragma unroll
            for (int j = 0; j < 4; j++) {
                float2 e0 = __half22float2(h2exp2(*(__half2*)&sacc[i][j][0]));
                float2 e1 = __half22float2(h2exp2(*(__half2*)&sacc[i][j][1]));
                zacc[i][j][0] += e0.x;
                zacc[i][j][1] += e0.y;
                zacc[i][j][2] += e1.x;
                zacc[i][j][3] += e1.y;
            }
    }
#pragma unroll
    for (int mt = 0; mt < 4; mt++)
#pragma unroll
        for (int nt = 0; nt < 4; nt++) {
            int row = qt + wm + mt * 16 + g;
            int col = kt + wn + nt * 8 + 2 * tg;
            __half* rp = g_r + ((size_t)b * SEQ + row) * SEQ + col;
            *(uint32_t*)rp = h2u(1.f / zacc[mt][nt][0], 1.f / zacc[mt][nt][1]);
            *(uint32_t*)(rp + (size_t)8 * SEQ) = h2u(1.f / zacc[mt][nt][2], 1.f / zacc[mt][nt][3]);
        }
}

// =====================================================================
// Pass B: ctx = sum_k 2^(q.k) * R * V   (GEMM1 fp16-acc, fragment reuse)
// =====================================================================
#define CQ_W (128 * 36)
#define CVT_W (64 * 68)
#define CR_W (128 * 68)
#define C_SMEM ((3 * CQ_W + 2 * CVT_W + 2 * CR_W) * 4)

__global__ __launch_bounds__(256) void attn_ctx() {
    extern __shared__ uint32_t smu[];
    uint32_t* sQ = smu;
    uint32_t* sK = smu + CQ_W;
    uint32_t* sV = smu + 3 * CQ_W;
    uint32_t* sR = smu + 3 * CQ_W + 2 * CVT_W;

    const int tid = threadIdx.x;
    const int b = blockIdx.z, h = blockIdx.x, qt = blockIdx.y * 128;
    const int w = tid >> 5, lane = tid & 31, g = lane >> 2, tg = lane & 3;
    const int wm = (w >> 2) * 64, wn = (w & 3) * 32;
    const int lrA = (lane & 7) + ((lane >> 3) & 1) * 8, lcA = (lane >> 4) * 4;
    const int lrB = (lane & 7) + (lane >> 4) * 8, lcB = ((lane >> 3) & 1) * 4;

    const int NT = SEQ / 128;

    auto load_kvr = [&](int t) {
        int slot = t & 1;
        const __half* kb = g_k + (size_t)(b * SEQ + t * 128) * DIM + h * HD;
        uint32_t* kd = sK + slot * CQ_W;
#pragma unroll
        for (int i = 0; i < 4; i++) {
            int c = tid + 256 * i;
            int r = c >> 3, cw = (c & 7) * 4;
            cpa16(kd + r * 36 + cw, kb + (size_t)r * DIM + cw * 2);
        }
        const __half* vtb = g_vT + ((size_t)(b * NH + h) * HD) * SEQ + t * 128;
        uint32_t* vd = sV + slot * CVT_W;
#pragma unroll
        for (int i = 0; i < 4; i++) {
            int c = tid + 256 * i;
            int r = c >> 4, cw = (c & 15) * 4;
            cpa16(vd + r * 68 + cw, vtb + (size_t)r * SEQ + cw * 2);
        }
        const __half* rb = g_r + ((size_t)b * SEQ + qt) * SEQ + t * 128;
        __half* rd = (__half*)(sR + slot * CR_W);
#pragma unroll
        for (int i = 0; i < 8; i++) {
            int c = tid + 256 * i;
            int r = c >> 4, ch = (c & 15) * 8;
            cpa16(rd + r * 136 + ch, rb + (size_t)r * SEQ + ch);
        }
    };

    {
        const __half* qb = g_q + (size_t)(b * SEQ + qt) * DIM + h * HD;
#pragma unroll
        for (int i = 0; i < 4; i++) {
            int c = tid + 256 * i;
            int r = c >> 3, cw = (c & 7) * 4;
            cpa16(sQ + r * 36 + cw, qb + (size_t)r * DIM + cw * 2);
        }
        load_kvr(0);
        cp_commit();
        load_kvr(1);
        cp_commit();
    }

    float cacc[4][8][4]{};

    for (int t = 0; t < NT; t++) {
        cp_wait<1>();
        __syncthreads();

        // GEMM1 (fp16 acc): S = Q @ K^T, log2-domain scores
        const uint32_t* kc = sK + (t & 1) * CQ_W;
        uint32_t sacc[4][4][2]{};
#pragma unroll
        for (int kw = 0; kw < 32; kw += 8) {
            uint32_t af[4][4], bf[4][2];
#pragma unroll
            for (int mt = 0; mt < 4; mt++)
                ldsm4(af[mt], sQ + (wm + mt * 16 + lrA) * 36 + kw + lcA);
#pragma unroll
            for (int np = 0; np < 2; np++) {
                uint32_t tmp[4];
                ldsm4(tmp, kc + (wn + np * 16 + lrB) * 36 + kw + lcB);
                bf[2 * np][0] = tmp[0];
                bf[2 * np][1] = tmp[1];
                bf[2 * np + 1][0] = tmp[2];
                bf[2 * np + 1][1] = tmp[3];
            }
#pragma unroll
            for (int mt = 0; mt < 4; mt++)
#pragma unroll
                for (int nt = 0; nt < 4; nt++) mma16h(sacc[mt][nt], af[mt], bf[nt]);
        }

        // Epilogue in registers: pa = 2^sacc * R  (A-fragments for GEMM2)
        const __half* rslot = (const __half*)(sR + (t & 1) * CR_W);
        uint32_t pa[4][2][4];
#pragma unroll
        for (int mt = 0; mt < 4; mt++)
#pragma unroll
            for (int kb = 0; kb < 2; kb++) {
                int row = wm + mt * 16 + g;
                int col = wn + (2 * kb) * 8 + 2 * tg;
                __half2 r0 = *(__half2*)(rslot + row * 136 + col);
                __half2 r1 = *(__half2*)(rslot + (row + 8) * 136 + col);
                __half2 r2 = *(__half2*)(rslot + row * 136 + col + 8);
                __half2 r3 = *(__half2*)(rslot + (row + 8) * 136 + col + 8);
                int lo = 2 * kb, hi = 2 * kb + 1;
                __half2 p0 = __hmul2(h2exp2(*(__half2*)&sacc[mt][lo][0]), r0);
                __half2 p1 = __hmul2(h2exp2(*(__half2*)&sacc[mt][lo][1]), r1);
                __half2 p2 = __hmul2(h2exp2(*(__half2*)&sacc[mt][hi][0]), r2);
                __half2 p3 = __hmul2(h2exp2(*(__half2*)&sacc[mt][hi][1]), r3);
                pa[mt][kb][0] = *(uint32_t*)&p0;
                pa[mt][kb][1] = *(uint32_t*)&p1;
                pa[mt][kb][2] = *(uint32_t*)&p2;
                pa[mt][kb][3] = *(uint32_t*)&p3;
            }

        // GEMM2 (fp32 acc): cacc += P_slice @ V_slice (64m x 64n x 32k per warp)
        const uint32_t* vslot = sV + (t & 1) * CVT_W;
        const int kwBase = wn >> 1;
#pragma unroll
        for (int kb = 0; kb < 2; kb++) {
            uint32_t bf[8][2];
#pragma unroll
            for (int np = 0; np < 4; np++) {
                uint32_t tmp[4];
                ldsm4(tmp, vslot + (np * 16 + lrB) * 68 + kwBase + kb * 8 + lcB);
                bf[2 * np][0] = tmp[0];
                bf[2 * np][1] = tmp[1];
                bf[2 * np + 1][0] = tmp[2];
                bf[2 * np + 1][1] = tmp[3];
            }
#pragma unroll
            for (int mt = 0; mt < 4; mt++)
#pragma unroll
                for (int nt = 0; nt < 8; nt++) mma16(cacc[mt][nt], pa[mt][kb], bf[nt]);
        }
        __syncthreads();

        if (t + 2 < NT) load_kvr(t + 2);
        cp_commit();
    }

    // 4-way k-slice reduction via sR (free now)
    float* red = (float*)sR;
    const int ks = w & 3, mg = w >> 2;
    float* rbase = red + mg * 64 * 68;
#pragma unroll
    for (int s = 1; s < 4; s++) {
        if (ks == s) {
#pragma unroll
            for (int mt = 0; mt < 4; mt++)
#pragma unroll
                for (int nt = 0; nt < 8; nt++) {
                    int row = mt * 16 + g;
                    int col = nt * 8 + 2 * tg;
                    if (s == 1) {
                        *(float2*)&rbase[row * 68 + col] = make_float2(cacc[mt][nt][0], cacc[mt][nt][1]);
                        *(float2*)&rbase[(row + 8) * 68 + col] = make_float2(cacc[mt][nt][2], cacc[mt][nt][3]);
                    } else {
                        float2 a0 = *(float2*)&rbase[row * 68 + col];
                        float2 a1 = *(float2*)&rbase[(row + 8) * 68 + col];
                        a0.x += cacc[mt][nt][0];
                        a0.y += cacc[mt][nt][1];
                        a1.x += cacc[mt][nt][2];
                        a1.y += cacc[mt][nt][3];
                        *(float2*)&rbase[row * 68 + col] = a0;
                        *(float2*)&rbase[(row + 8) * 68 + col] = a1;
                    }
                }
        }
        __syncthreads();
    }
    if (ks == 0) {
        __half* cb = g_ctx + (size_t)(b * SEQ + qt) * DIM + h * HD;
#pragma unroll
        for (int mt = 0; mt < 4; mt++)
#pragma unroll
            for (int nt = 0; nt < 8; nt++) {
                int row = mt * 16 + g;
                int col = nt * 8 + 2 * tg;
                float2 o0 = *(float2*)&rbase[row * 68 + col];
                float2 o1 = *(float2*)&rbase[(row + 8) * 68 + col];
                *(uint32_t*)(cb + (size_t)(wm + row) * DIM + col) =
                    h2u(o0.x + cacc[mt][nt][0], o0.y + cacc[mt][nt][1]);
                *(uint32_t*)(cb + (size_t)(wm + row + 8) * DIM + col) =
                    h2u(o1.x + cacc[mt][nt][2], o1.y + cacc[mt][nt][3]);
            }
    }
}

// =====================================================================
extern "C" void kernel_launch(void* const* d_in, const int* in_sizes, int n_in,
                              void* d_out, int out_size) {
    const float* x = (const float*)d_in[0];
    const float* wq = (const float*)d_in[1];
    const float* wk = (const float*)d_in[2];
    const float* wv = (const float*)d_in[3];
    const float* wo = (const float*)d_in[4];
    float* out = (float*)d_out;

    __half *ctx, *xr, *wr;
    cudaGetSymbolAddress((void**)&ctx, g_ctx);
    cudaGetSymbolAddress((void**)&xr, g_x);
    cudaGetSymbolAddress((void**)&wr, g_w);

    static int attr_done = 0;
    if (!attr_done) {
        cudaFuncSetAttribute(gemm_fp16, cudaFuncAttributeMaxDynamicSharedMemorySize, G_SMEM);
        cudaFuncSetAttribute(gemm_qkv, cudaFuncAttributeMaxDynamicSharedMemorySize, G_SMEM);
        cudaFuncSetAttribute(attn_z, cudaFuncAttributeMaxDynamicSharedMemorySize, Z_SMEM);
        cudaFuncSetAttribute(attn_ctx, cudaFuncAttributeMaxDynamicSharedMemorySize, C_SMEM);
        attr_done = 1;
    }

    round_x_h<<<2048, 256>>>(x);
    round_w_t<<<dim3(32, 32, 4), 256>>>(wq, wk, wv, wo);

    gemm_qkv<<<dim3(DIM / 256, MTOT / 128, 3), 256, G_SMEM>>>(xr);

    transpose_v<<<dim3(SEQ / 32, DIM / 32, BATCH), 256>>>();

    attn_z<<<dim3(SEQ / 128, SEQ / 128, BATCH), 256, Z_SMEM>>>();

    attn_ctx<<<dim3(NH, SEQ / 128, BATCH), 256, C_SMEM>>>();

    gemm_fp16<<<dim3(DIM / 256, MTOT / 128), 256, G_SMEM>>>(ctx, wr + 3 * DIM * DIM, out, 0, 1.0f);
}